// round 4
// baseline (speedup 1.0000x reference)
#include <cuda_runtime.h>
#include <cuda_bf16.h>

// ---------------- problem constants ----------------
#define Bn   32
#define Tn   8
#define Dd   768
#define DHh  3072
#define Ff   512
#define MHh  128
#define Pp   196
#define BP   (Bn*Pp)

// ---------------- device scratch (split bf16 planes + fp32) ----------------
__device__ __nv_bfloat16 g_pHi [(long)BP*Dd],  g_pLo [(long)BP*Dd];
__device__ __nv_bfloat16 g_hHi [(long)BP*Dd],  g_hLo [(long)BP*Dd];
__device__ __nv_bfloat16 g_hbHi[(long)BP*Dd],  g_hbLo[(long)BP*Dd];
__device__ __nv_bfloat16 g_W1sHi[(long)Dd*Dd],   g_W1sLo[(long)Dd*Dd];
__device__ __nv_bfloat16 g_W2sHi[(long)Dd*DHh],  g_W2sLo[(long)Dd*DHh];
__device__ __nv_bfloat16 g_W1bHi[(long)Bn*Dd*Dd],  g_W1bLo[(long)Bn*Dd*Dd];
__device__ __nv_bfloat16 g_W2bHi[(long)Bn*Dd*DHh], g_W2bLo[(long)Bn*Dd*DHh];
__device__ float g_h2m0[Bn*DHh], g_h2m1[Bn*DHh];
__device__ float g_base[Bn*Ff],  g_coef[Bn*Tn];
__device__ float g_b1b[Bn*Dd],   g_b2b[Bn*DHh];
__device__ float g_z0[Bn*Ff],    g_y[(long)Tn*Bn*Ff];

// ---------------- bf16 split helpers ----------------
__device__ __forceinline__ void split_pair(float a, float b, unsigned& hi, unsigned& lo) {
    __nv_bfloat16 ha = __float2bfloat16(a);
    __nv_bfloat16 hb = __float2bfloat16(b);
    __nv_bfloat16 la = __float2bfloat16(a - __bfloat162float(ha));
    __nv_bfloat16 lb = __float2bfloat16(b - __bfloat162float(hb));
    __nv_bfloat162 h2 = __halves2bfloat162(ha, hb);
    __nv_bfloat162 l2 = __halves2bfloat162(la, lb);
    hi = *reinterpret_cast<unsigned*>(&h2);
    lo = *reinterpret_cast<unsigned*>(&l2);
}
__device__ __forceinline__ void split_quad(float4 v, uint2& hi, uint2& lo) {
    split_pair(v.x, v.y, hi.x, lo.x);
    split_pair(v.z, v.w, hi.y, lo.y);
}

__device__ __forceinline__ void mma_bf16(float* c, const unsigned* a, const unsigned* b) {
    asm volatile(
        "mma.sync.aligned.m16n8k16.row.col.f32.bf16.bf16.f32 "
        "{%0,%1,%2,%3}, {%4,%5,%6,%7}, {%8,%9}, {%0,%1,%2,%3};"
        : "+f"(c[0]), "+f"(c[1]), "+f"(c[2]), "+f"(c[3])
        : "r"(a[0]), "r"(a[1]), "r"(a[2]), "r"(a[3]), "r"(b[0]), "r"(b[1]));
}
__device__ __forceinline__ void ldsm_x4(unsigned* r, unsigned addr) {
    asm volatile("ldmatrix.sync.aligned.m8n8.x4.shared.b16 {%0,%1,%2,%3}, [%4];"
                 : "=r"(r[0]), "=r"(r[1]), "=r"(r[2]), "=r"(r[3]) : "r"(addr));
}
__device__ __forceinline__ void ldsm_x2t(unsigned* r, unsigned addr) {
    asm volatile("ldmatrix.sync.aligned.m8n8.x2.trans.shared.b16 {%0,%1}, [%2];"
                 : "=r"(r[0]), "=r"(r[1]) : "r"(addr));
}

// ---------------- patchify: x -> split planes ----------------
__global__ void patchify_split(const float* __restrict__ x,
                               __nv_bfloat16* __restrict__ pHi,
                               __nv_bfloat16* __restrict__ pLo) {
    long q = (long)blockIdx.x * blockDim.x + threadIdx.x;
    if (q >= (long)BP * Dd / 2) return;
    int d2   = (int)(q % (Dd / 2));
    long rem = q / (Dd / 2);
    int patch = (int)(rem % Pp);
    int b     = (int)(rem / Pp);
    int d  = d2 * 2;
    int pi = patch / 14, pj = patch % 14;
    int c = d >> 8, r = (d >> 4) & 15, s = d & 15;
    float2 v = *(const float2*)(x + ((long)(b * 3 + c) * 224 + pi * 16 + r) * 224 + pj * 16 + s);
    unsigned hi, lo;
    split_pair(v.x, v.y, hi, lo);
    long e = rem * Dd + d;
    *(unsigned*)(pHi + e) = hi;
    *(unsigned*)(pLo + e) = lo;
}

// ---------------- split a fp32 weight into planes ----------------
__global__ void split_w(const float* __restrict__ src,
                        __nv_bfloat16* __restrict__ hi, __nv_bfloat16* __restrict__ lo,
                        long n4) {
    long i = (long)blockIdx.x * blockDim.x + threadIdx.x;
    if (i >= n4) return;
    long e = i * 4;
    float4 v = *(const float4*)(src + e);
    uint2 h, l;
    split_quad(v, h, l);
    *(uint2*)(hi + e) = h;
    *(uint2*)(lo + e) = l;
}

// ---------------- zero two buffers ----------------
__global__ void zero2(float* a, float* b, int n) {
    int i = blockIdx.x * blockDim.x + threadIdx.x;
    if (i < n) { a[i] = 0.f; b[i] = 0.f; }
}

// ---------------- tensor-core batched GEMM (pre-split planes, 3 passes) ----------------
// mode 0: write relu output as split planes (cHi/cLo)
// mode 1: fused mean-pool: atomicAdd relu'd column means into pool[sample][col]
#define BM 128
#define BN 64
#define BK 16
#define APITCH 24
#define BPITCH 72
#define A_PLANE (BM*APITCH)
#define B_PLANE (BK*BPITCH)

__global__ void __launch_bounds__(256, 2) mma_gemm2(
    const __nv_bfloat16* __restrict__ aHi, const __nv_bfloat16* __restrict__ aLo, long aStride,
    const __nv_bfloat16* __restrict__ wHi, const __nv_bfloat16* __restrict__ wLo, long wStride,
    const float* __restrict__ bias, long biasStride,
    __nv_bfloat16* cHi, __nv_bfloat16* cLo, long cStride,
    float* pool,
    int M, int N, int K, int mode)
{
    int bz = blockIdx.z;
    aHi  += (long)bz * aStride;  aLo += (long)bz * aStride;
    wHi  += (long)bz * wStride;  wLo += (long)bz * wStride;
    bias += (long)bz * biasStride;

    __shared__ __nv_bfloat16 sA[2][2][A_PLANE];
    __shared__ __nv_bfloat16 sB[2][2][B_PLANE];

    int m0 = blockIdx.x * BM;
    int n0 = blockIdx.y * BN;
    int tid  = threadIdx.x;
    int lane = tid & 31;
    int warp = tid >> 5;
    int wm = warp & 3;
    int wn = warp >> 2;

    unsigned aBase = (unsigned)__cvta_generic_to_shared(&sA[0][0][0]);
    unsigned bBase = (unsigned)__cvta_generic_to_shared(&sB[0][0][0]);
    int aRowInWarp = (lane & 15);
    int aColOff    = (lane >> 4) * 8;
    unsigned aAddr[2];
    #pragma unroll
    for (int mt = 0; mt < 2; mt++)
        aAddr[mt] = aBase + (unsigned)(((wm * 32 + mt * 16 + aRowInWarp) * APITCH + aColOff) * 2);
    unsigned bAddr[4];
    #pragma unroll
    for (int nt = 0; nt < 4; nt++)
        bAddr[nt] = bBase + (unsigned)(((lane & 15) * BPITCH + wn * 32 + nt * 8) * 2);

    const unsigned A_PLANE_B = A_PLANE * 2;
    const unsigned A_BUF_B   = 2 * A_PLANE_B;
    const unsigned B_PLANE_B = B_PLANE * 2;
    const unsigned B_BUF_B   = 2 * B_PLANE_B;

    uint2 aH[2], aL[2], bH, bL;
    int ntile = K / BK;

    auto loadTile = [&](int t) {
        int k0 = t * BK;
        #pragma unroll
        for (int i = 0; i < 2; i++) {
            int idx = tid + i * 256;
            int row = idx >> 2, kq = idx & 3;
            int gm = m0 + row;
            if (gm < M) {
                long off = (long)gm * K + k0 + kq * 4;
                aH[i] = *(const uint2*)(aHi + off);
                aL[i] = *(const uint2*)(aLo + off);
            } else {
                aH[i] = make_uint2(0u, 0u);
                aL[i] = make_uint2(0u, 0u);
            }
        }
        {
            int krow = tid >> 4, nq = tid & 15;
            long off = (long)(k0 + krow) * N + n0 + nq * 4;
            bH = *(const uint2*)(wHi + off);
            bL = *(const uint2*)(wLo + off);
        }
    };
    auto storeTile = [&](int buf) {
        #pragma unroll
        for (int i = 0; i < 2; i++) {
            int idx = tid + i * 256;
            int row = idx >> 2, kq = idx & 3;
            int e = row * APITCH + kq * 4;
            *(uint2*)(&sA[buf][0][e]) = aH[i];
            *(uint2*)(&sA[buf][1][e]) = aL[i];
        }
        {
            int krow = tid >> 4, nq = tid & 15;
            int e = krow * BPITCH + nq * 4;
            *(uint2*)(&sB[buf][0][e]) = bH;
            *(uint2*)(&sB[buf][1][e]) = bL;
        }
    };

    float acc[2][4][4];
    #pragma unroll
    for (int i = 0; i < 2; i++)
        #pragma unroll
        for (int j = 0; j < 4; j++)
            #pragma unroll
            for (int k = 0; k < 4; k++) acc[i][j][k] = 0.f;

    loadTile(0);
    storeTile(0);
    if (ntile > 1) loadTile(1);
    __syncthreads();

    for (int t = 0; t < ntile; t++) {
        int cur = t & 1;
        if (t + 1 < ntile) {
            storeTile((t + 1) & 1);
            if (t + 2 < ntile) loadTile(t + 2);
        }
        unsigned aOff = (unsigned)cur * A_BUF_B;
        unsigned bOff = (unsigned)cur * B_BUF_B;

        unsigned afr[2][2][4];
        #pragma unroll
        for (int mt = 0; mt < 2; mt++) {
            ldsm_x4(afr[0][mt], aAddr[mt] + aOff);
            ldsm_x4(afr[1][mt], aAddr[mt] + aOff + A_PLANE_B);
        }
        unsigned bfr[2][4][2];
        #pragma unroll
        for (int nt = 0; nt < 4; nt++) {
            ldsm_x2t(bfr[0][nt], bAddr[nt] + bOff);
            ldsm_x2t(bfr[1][nt], bAddr[nt] + bOff + B_PLANE_B);
        }
        #pragma unroll
        for (int mt = 0; mt < 2; mt++)
            #pragma unroll
            for (int nt = 0; nt < 4; nt++) {
                mma_bf16(acc[mt][nt], afr[0][mt], bfr[0][nt]);  // hi*hi
                mma_bf16(acc[mt][nt], afr[1][mt], bfr[0][nt]);  // lo*hi
                mma_bf16(acc[mt][nt], afr[0][mt], bfr[1][nt]);  // hi*lo
            }
        __syncthreads();
    }

    int g  = lane >> 2;
    int c4 = lane & 3;

    if (mode == 0) {
        // relu + split-store planes
        cHi += (long)bz * cStride;
        cLo += (long)bz * cStride;
        #pragma unroll
        for (int mt = 0; mt < 2; mt++) {
            int r0 = m0 + wm * 32 + mt * 16 + g;
            #pragma unroll
            for (int nt = 0; nt < 4; nt++) {
                int col = n0 + wn * 32 + nt * 8 + 2 * c4;
                float bx = bias[col], by = bias[col + 1];
                if (r0 < M) {
                    float v0 = fmaxf(acc[mt][nt][0] + bx, 0.f);
                    float v1 = fmaxf(acc[mt][nt][1] + by, 0.f);
                    unsigned hi, lo;
                    split_pair(v0, v1, hi, lo);
                    *(unsigned*)(cHi + (long)r0 * N + col) = hi;
                    *(unsigned*)(cLo + (long)r0 * N + col) = lo;
                }
                if (r0 + 8 < M) {
                    float v0 = fmaxf(acc[mt][nt][2] + bx, 0.f);
                    float v1 = fmaxf(acc[mt][nt][3] + by, 0.f);
                    unsigned hi, lo;
                    split_pair(v0, v1, hi, lo);
                    *(unsigned*)(cHi + (long)(r0 + 8) * N + col) = hi;
                    *(unsigned*)(cLo + (long)(r0 + 8) * N + col) = lo;
                }
            }
        }
    } else {
        // fused mean-pool: relu, per-warp column sums, atomicAdd into pool
        int warpRow0 = m0 + wm * 32;
        if (warpRow0 < M) {
            int sLocal = warpRow0 / Pp;
            int sampA  = bz + sLocal;
            int bnd    = (sLocal + 1) * Pp - warpRow0;   // local rows < bnd -> sampA
            bool has2  = (bnd < 32) && (warpRow0 + bnd) < M;
            float t0[8], t1[8];
            #pragma unroll
            for (int s = 0; s < 8; s++) { t0[s] = 0.f; t1[s] = 0.f; }
            #pragma unroll
            for (int mt = 0; mt < 2; mt++) {
                int lr0 = mt * 16 + g;
                int lr1 = lr0 + 8;
                bool ok0 = (warpRow0 + lr0) < M;
                bool ok1 = (warpRow0 + lr1) < M;
                #pragma unroll
                for (int nt = 0; nt < 4; nt++) {
                    int col = n0 + wn * 32 + nt * 8 + 2 * c4;
                    float bx = bias[col], by = bias[col + 1];
                    float a0 = fmaxf(acc[mt][nt][0] + bx, 0.f);
                    float a1 = fmaxf(acc[mt][nt][1] + by, 0.f);
                    float a2 = fmaxf(acc[mt][nt][2] + bx, 0.f);
                    float a3 = fmaxf(acc[mt][nt][3] + by, 0.f);
                    int s0 = nt * 2, s1 = nt * 2 + 1;
                    if (ok0) {
                        if (lr0 < bnd) { t0[s0] += a0; t0[s1] += a1; }
                        else           { t1[s0] += a0; t1[s1] += a1; }
                    }
                    if (ok1) {
                        if (lr1 < bnd) { t0[s0] += a2; t0[s1] += a3; }
                        else           { t1[s0] += a2; t1[s1] += a3; }
                    }
                }
            }
            // reduce over g (lanes differing in bits 2..4)
            #pragma unroll
            for (int ofs = 4; ofs < 32; ofs <<= 1) {
                #pragma unroll
                for (int s = 0; s < 8; s++)
                    t0[s] += __shfl_xor_sync(0xFFFFFFFFu, t0[s], ofs);
            }
            if (has2) {
                #pragma unroll
                for (int ofs = 4; ofs < 32; ofs <<= 1) {
                    #pragma unroll
                    for (int s = 0; s < 8; s++)
                        t1[s] += __shfl_xor_sync(0xFFFFFFFFu, t1[s], ofs);
                }
            }
            if (lane < 4) {
                const float inv = 1.f / (float)Pp;
                #pragma unroll
                for (int nt = 0; nt < 4; nt++) {
                    #pragma unroll
                    for (int cp = 0; cp < 2; cp++) {
                        int col = n0 + wn * 32 + nt * 8 + 2 * lane + cp;
                        atomicAdd(&pool[(long)sampA * N + col], t0[nt * 2 + cp] * inv);
                        if (has2)
                            atomicAdd(&pool[(long)(sampA + 1) * N + col], t1[nt * 2 + cp] * inv);
                    }
                }
            }
        }
    }
}

// ---------------- small-M GEMM with in-block split-K (fp32) ----------------
__global__ void rowgemm_kernel(const float* __restrict__ A,
                               const float* __restrict__ W, long wStride,
                               const float* __restrict__ bias, long biasStride,
                               float* __restrict__ C, int N, int K)
{
    int b  = blockIdx.x;
    int nl = threadIdx.x & 31;
    int kg = threadIdx.x >> 5;
    int n  = blockIdx.y * 32 + nl;
    const float* a = A + (long)b * K;
    const float* w = W + (long)b * wStride;
    int kchunk = K / 8;
    float acc = 0.f;
    for (int k = kg * kchunk; k < (kg + 1) * kchunk; k++)
        acc = fmaf(a[k], w[(long)k * N + n], acc);
    __shared__ float red[8][32];
    red[kg][nl] = acc;
    __syncthreads();
    if (kg == 0) {
        float s = acc;
        #pragma unroll
        for (int j = 1; j < 8; j++) s += red[j][nl];
        C[(long)b * N + n] = s + bias[(long)b * biasStride + n];
    }
}

// ---------------- MetaNet ----------------
__global__ void meta_kernel(const float* __restrict__ base,
                            const float* __restrict__ mW1, const float* __restrict__ mb1,
                            const float* __restrict__ mW2, const float* __restrict__ mb2,
                            float* __restrict__ coef)
{
    int b = blockIdx.x;
    __shared__ float br[Ff];
    __shared__ float hid[MHh];
    int t = threadIdx.x;
    for (int i = t; i < Ff; i += MHh) br[i] = base[b * Ff + i];
    __syncthreads();
    float acc = mb1[t];
    for (int e = 0; e < Ff; e++) acc = fmaf(br[e], mW1[e * MHh + t], acc);
    hid[t] = fmaxf(acc, 0.f);
    __syncthreads();
    if (t < Tn) {
        float c = mb2[t];
        for (int j = 0; j < MHh; j++) c = fmaf(hid[j], mW2[j * Tn + t], c);
        coef[b * Tn + t] = c;
    }
}

// ---------------- compose biases (fp32) ----------------
__global__ void compose_kernel(const float* __restrict__ W, const float* __restrict__ dW,
                               const float* __restrict__ coef, float* __restrict__ out, long S)
{
    __shared__ float cs[Bn * Tn];
    if (threadIdx.x < Bn * Tn) cs[threadIdx.x] = coef[threadIdx.x];
    __syncthreads();
    long i = (long)blockIdx.x * blockDim.x + threadIdx.x;
    if (i >= S) return;
    float w = W[i];
    float d[Tn];
    #pragma unroll
    for (int t = 0; t < Tn; t++) d[t] = dW[(long)t * S + i];
    #pragma unroll 4
    for (int b = 0; b < Bn; b++) {
        float v = w;
        #pragma unroll
        for (int t = 0; t < Tn; t++) v = fmaf(cs[b * Tn + t], d[t], v);
        out[(long)b * S + i] = v;
    }
}

// ---------------- compose weights -> split planes ----------------
__global__ void compose_split(const float* __restrict__ W, const float* __restrict__ dW,
                              const float* __restrict__ coef,
                              __nv_bfloat16* __restrict__ oHi, __nv_bfloat16* __restrict__ oLo,
                              long S)
{
    __shared__ float cs[Bn * Tn];
    if (threadIdx.x < Bn * Tn) cs[threadIdx.x] = coef[threadIdx.x];
    __syncthreads();
    long q = (long)blockIdx.x * blockDim.x + threadIdx.x;
    if (q >= S / 4) return;
    long e = q * 4;
    float4 w = *(const float4*)(W + e);
    float4 d[Tn];
    #pragma unroll
    for (int t = 0; t < Tn; t++) d[t] = *(const float4*)(dW + (long)t * S + e);
    for (int b = 0; b < Bn; b++) {
        float4 v = w;
        #pragma unroll
        for (int t = 0; t < Tn; t++) {
            float c = cs[b * Tn + t];
            v.x = fmaf(c, d[t].x, v.x);
            v.y = fmaf(c, d[t].y, v.y);
            v.z = fmaf(c, d[t].z, v.z);
            v.w = fmaf(c, d[t].w, v.w);
        }
        uint2 hi, lo;
        split_quad(v, hi, lo);
        *(uint2*)(oHi + (long)b * S + e) = hi;
        *(uint2*)(oLo + (long)b * S + e) = lo;
    }
}

// ---------------- y[t,b,n] = h2m[b,:] @ dW3[t,:,n] ----------------
#define YNC 16
__global__ void ydw3_kernel(const float* __restrict__ h2m, const float* __restrict__ dW3,
                            float* __restrict__ y)
{
    int t  = blockIdx.y;
    int n0 = blockIdx.x * YNC;
    const float* w = dW3 + (long)t * DHh * Ff;
    __shared__ float sw[16][YNC];
    __shared__ float sh[Bn][16];
    int tid = threadIdx.x;
    int b  = tid >> 3;
    int nl = tid & 7;
    float acc0 = 0.f, acc1 = 0.f;
    for (int k0 = 0; k0 < DHh; k0 += 16) {
        if (tid < 64) {
            int kk = tid >> 2, nq = tid & 3;
            float4 v = *(const float4*)(w + (long)(k0 + kk) * Ff + n0 + nq * 4);
            sw[kk][nq * 4 + 0] = v.x; sw[kk][nq * 4 + 1] = v.y;
            sw[kk][nq * 4 + 2] = v.z; sw[kk][nq * 4 + 3] = v.w;
        }
        if (tid >= 128) {
            int tt = tid - 128;
            int bb = tt >> 2, kq = tt & 3;
            float4 v = *(const float4*)(h2m + (long)bb * DHh + k0 + kq * 4);
            sh[bb][kq * 4 + 0] = v.x; sh[bb][kq * 4 + 1] = v.y;
            sh[bb][kq * 4 + 2] = v.z; sh[bb][kq * 4 + 3] = v.w;
        }
        __syncthreads();
        #pragma unroll
        for (int kk = 0; kk < 16; kk++) {
            float a = sh[b][kk];
            acc0 = fmaf(a, sw[kk][nl * 2 + 0], acc0);
            acc1 = fmaf(a, sw[kk][nl * 2 + 1], acc1);
        }
        __syncthreads();
    }
    long o = ((long)t * Bn + b) * Ff + n0 + nl * 2;
    y[o]     = acc0;
    y[o + 1] = acc1;
}

// ---------------- final combine ----------------
__global__ void combine_kernel(const float* __restrict__ z0, const float* __restrict__ y,
                               const float* __restrict__ coef, const float* __restrict__ db3,
                               float* __restrict__ out)
{
    int i = blockIdx.x * blockDim.x + threadIdx.x;
    if (i >= Bn * Ff) return;
    int b = i / Ff, n = i % Ff;
    float v = z0[i];
    #pragma unroll
    for (int t = 0; t < Tn; t++)
        v = fmaf(coef[b * Tn + t], y[((long)t * Bn + b) * Ff + n] + db3[t * Ff + n], v);
    out[i] = v;
}

// ---------------- launch ----------------
extern "C" void kernel_launch(void* const* d_in, const int* in_sizes, int n_in,
                              void* d_out, int out_size)
{
    const float* x   = (const float*)d_in[0];
    const float* W1  = (const float*)d_in[1];
    const float* b1  = (const float*)d_in[2];
    const float* W2  = (const float*)d_in[3];
    const float* b2  = (const float*)d_in[4];
    const float* W3  = (const float*)d_in[5];
    const float* b3  = (const float*)d_in[6];
    const float* dW1 = (const float*)d_in[7];
    const float* db1 = (const float*)d_in[8];
    const float* dW2 = (const float*)d_in[9];
    const float* db2 = (const float*)d_in[10];
    const float* dW3 = (const float*)d_in[11];
    const float* db3 = (const float*)d_in[12];
    const float* mW1 = (const float*)d_in[13];
    const float* mb1 = (const float*)d_in[14];
    const float* mW2 = (const float*)d_in[15];
    const float* mb2 = (const float*)d_in[16];
    float* out = (float*)d_out;

    __nv_bfloat16 *pHi, *pLo, *hHi, *hLo, *hbHi, *hbLo;
    __nv_bfloat16 *W1sHi, *W1sLo, *W2sHi, *W2sLo;
    __nv_bfloat16 *W1bHi, *W1bLo, *W2bHi, *W2bLo;
    float *h2m0, *h2m1, *base, *coef, *b1b, *b2b, *z0, *y;
    cudaGetSymbolAddress((void**)&pHi,  g_pHi);   cudaGetSymbolAddress((void**)&pLo,  g_pLo);
    cudaGetSymbolAddress((void**)&hHi,  g_hHi);   cudaGetSymbolAddress((void**)&hLo,  g_hLo);
    cudaGetSymbolAddress((void**)&hbHi, g_hbHi);  cudaGetSymbolAddress((void**)&hbLo, g_hbLo);
    cudaGetSymbolAddress((void**)&W1sHi, g_W1sHi); cudaGetSymbolAddress((void**)&W1sLo, g_W1sLo);
    cudaGetSymbolAddress((void**)&W2sHi, g_W2sHi); cudaGetSymbolAddress((void**)&W2sLo, g_W2sLo);
    cudaGetSymbolAddress((void**)&W1bHi, g_W1bHi); cudaGetSymbolAddress((void**)&W1bLo, g_W1bLo);
    cudaGetSymbolAddress((void**)&W2bHi, g_W2bHi); cudaGetSymbolAddress((void**)&W2bLo, g_W2bLo);
    cudaGetSymbolAddress((void**)&h2m0, g_h2m0);  cudaGetSymbolAddress((void**)&h2m1, g_h2m1);
    cudaGetSymbolAddress((void**)&base, g_base);  cudaGetSymbolAddress((void**)&coef, g_coef);
    cudaGetSymbolAddress((void**)&b1b,  g_b1b);   cudaGetSymbolAddress((void**)&b2b,  g_b2b);
    cudaGetSymbolAddress((void**)&z0,   g_z0);    cudaGetSymbolAddress((void**)&y,    g_y);

    // 1) patchify -> split planes
    {
        long n = (long)BP * Dd / 2;
        patchify_split<<<(unsigned)((n + 255) / 256), 256>>>(x, pHi, pLo);
    }
    // 2) pre-split base weights
    split_w<<<(unsigned)(((long)Dd * Dd / 4 + 255) / 256), 256>>>(W1, W1sHi, W1sLo, (long)Dd * Dd / 4);
    split_w<<<(unsigned)(((long)Dd * DHh / 4 + 255) / 256), 256>>>(W2, W2sHi, W2sLo, (long)Dd * DHh / 4);
    // 3) zero pool accumulators
    zero2<<<(Bn * DHh + 255) / 256, 256>>>(h2m0, h2m1, Bn * DHh);

    // 4) base layer1: h = relu(p @ W1 + b1), split planes out
    mma_gemm2<<<dim3(BP / BM, Dd / BN, 1), 256>>>(
        pHi, pLo, 0, W1sHi, W1sLo, 0, b1, 0,
        hHi, hLo, 0, nullptr, BP, Dd, Dd, 0);

    // 5) base layer2 + fused mean-pool -> h2m0
    mma_gemm2<<<dim3(BP / BM, DHh / BN, 1), 256>>>(
        hHi, hLo, 0, W2sHi, W2sLo, 0, b2, 0,
        nullptr, nullptr, 0, h2m0, BP, DHh, Dd, 1);

    // 6) base = h2m0 @ W3 + b3
    rowgemm_kernel<<<dim3(Bn, Ff / 32), 256>>>(h2m0, W3, 0, b3, 0, base, Ff, DHh);

    // 7) MetaNet -> coefs
    meta_kernel<<<Bn, MHh>>>(base, mW1, mb1, mW2, mb2, coef);

    // 8) compose biases (fp32) and weights (split planes)
    compose_kernel<<<(Dd  + 255) / 256, 256>>>(b1, db1, coef, b1b, Dd);
    compose_kernel<<<(DHh + 255) / 256, 256>>>(b2, db2, coef, b2b, DHh);
    {
        long S1 = (long)Dd * Dd;
        long S2 = (long)Dd * DHh;
        compose_split<<<(unsigned)((S1 / 4 + 255) / 256), 256>>>(W1, dW1, coef, W1bHi, W1bLo, S1);
        compose_split<<<(unsigned)((S2 / 4 + 255) / 256), 256>>>(W2, dW2, coef, W2bHi, W2bLo, S2);
    }

    // 9) adapted layer1 (batched): hb = relu(p @ W1b + b1b)
    mma_gemm2<<<dim3((Pp + BM - 1) / BM, Dd / BN, Bn), 256>>>(
        pHi, pLo, (long)Pp * Dd,
        W1bHi, W1bLo, (long)Dd * Dd,
        b1b, (long)Dd,
        hbHi, hbLo, (long)Pp * Dd, nullptr,
        Pp, Dd, Dd, 0);

    // 10) adapted layer2 + fused mean-pool -> h2m1
    mma_gemm2<<<dim3((Pp + BM - 1) / BM, DHh / BN, Bn), 256>>>(
        hbHi, hbLo, (long)Pp * Dd,
        W2bHi, W2bLo, (long)Dd * DHh,
        b2b, (long)DHh,
        nullptr, nullptr, 0, h2m1,
        Pp, DHh, Dd, 1);

    // 11) z0 = h2m1 @ W3 + b3
    rowgemm_kernel<<<dim3(Bn, Ff / 32), 256>>>(h2m1, W3, 0, b3, 0, z0, Ff, DHh);

    // 12) y[t,b,:] = h2m1[b,:] @ dW3[t]
    ydw3_kernel<<<dim3(Ff / YNC, Tn), 256>>>(h2m1, dW3, y);

    // 13) out = z0 + sum_t coef*(y + db3)
    combine_kernel<<<(Bn * Ff + 255) / 256, 256>>>(z0, y, coef, db3, out);
}

// round 5
// speedup vs baseline: 1.1314x; 1.1314x over previous
#include <cuda_runtime.h>
#include <cuda_bf16.h>

// ---------------- problem constants ----------------
#define Bn   32
#define Tn   8
#define Dd   768
#define DHh  3072
#define Ff   512
#define MHh  128
#define Pp   196
#define BP   (Bn*Pp)

// ---------------- device scratch ----------------
// Interleaved split format: one uint2 per 2 fp32 elems = {bf16x2 hi, bf16x2 lo}.
__device__ uint2 g_pP  [(long)BP*Dd/2];
__device__ uint2 g_hP  [(long)BP*Dd/2];
__device__ uint2 g_hbP [(long)BP*Dd/2];
__device__ uint2 g_W1sP[(long)Dd*Dd/2];
__device__ uint2 g_W2sP[(long)Dd*DHh/2];
__device__ uint2 g_W1bP[(long)Bn*Dd*Dd/2];
__device__ uint2 g_W2bP[(long)Bn*Dd*DHh/2];
__device__ float g_h2m0[Bn*DHh], g_h2m1[Bn*DHh];
__device__ float g_base[Bn*Ff],  g_coef[Bn*Tn];
__device__ float g_b1b[Bn*Dd],   g_b2b[Bn*DHh];
__device__ float g_z0[Bn*Ff],    g_y[(long)Tn*Bn*Ff];

// ---------------- bf16 split helpers ----------------
__device__ __forceinline__ void split_pair(float a, float b, unsigned& hi, unsigned& lo) {
    __nv_bfloat16 ha = __float2bfloat16(a);
    __nv_bfloat16 hb = __float2bfloat16(b);
    __nv_bfloat16 la = __float2bfloat16(a - __bfloat162float(ha));
    __nv_bfloat16 lb = __float2bfloat16(b - __bfloat162float(hb));
    __nv_bfloat162 h2 = __halves2bfloat162(ha, hb);
    __nv_bfloat162 l2 = __halves2bfloat162(la, lb);
    hi = *reinterpret_cast<unsigned*>(&h2);
    lo = *reinterpret_cast<unsigned*>(&l2);
}
// 4 fp32 -> interleaved uint4 {hi01, lo01, hi23, lo23}
__device__ __forceinline__ uint4 split_quad_i(float4 v) {
    uint4 r;
    split_pair(v.x, v.y, r.x, r.y);
    split_pair(v.z, v.w, r.z, r.w);
    return r;
}

__device__ __forceinline__ void mma_bf16(float* c, const unsigned* a, const unsigned* b) {
    asm volatile(
        "mma.sync.aligned.m16n8k16.row.col.f32.bf16.bf16.f32 "
        "{%0,%1,%2,%3}, {%4,%5,%6,%7}, {%8,%9}, {%0,%1,%2,%3};"
        : "+f"(c[0]), "+f"(c[1]), "+f"(c[2]), "+f"(c[3])
        : "r"(a[0]), "r"(a[1]), "r"(a[2]), "r"(a[3]), "r"(b[0]), "r"(b[1]));
}
__device__ __forceinline__ void ldsm_x4(unsigned* r, unsigned addr) {
    asm volatile("ldmatrix.sync.aligned.m8n8.x4.shared.b16 {%0,%1,%2,%3}, [%4];"
                 : "=r"(r[0]), "=r"(r[1]), "=r"(r[2]), "=r"(r[3]) : "r"(addr));
}
__device__ __forceinline__ void ldsm_x4t(unsigned* r, unsigned addr) {
    asm volatile("ldmatrix.sync.aligned.m8n8.x4.trans.shared.b16 {%0,%1,%2,%3}, [%4];"
                 : "=r"(r[0]), "=r"(r[1]), "=r"(r[2]), "=r"(r[3]) : "r"(addr));
}

// ---------------- patchify: x -> interleaved split ----------------
__global__ void patchify_split(const float* __restrict__ x, uint2* __restrict__ pP) {
    long q = (long)blockIdx.x * blockDim.x + threadIdx.x;
    if (q >= (long)BP * Dd / 2) return;
    int d2   = (int)(q % (Dd / 2));
    long rem = q / (Dd / 2);
    int patch = (int)(rem % Pp);
    int b     = (int)(rem / Pp);
    int d  = d2 * 2;
    int pi = patch / 14, pj = patch % 14;
    int c = d >> 8, r = (d >> 4) & 15, s = d & 15;
    float2 v = *(const float2*)(x + ((long)(b * 3 + c) * 224 + pi * 16 + r) * 224 + pj * 16 + s);
    unsigned hi, lo;
    split_pair(v.x, v.y, hi, lo);
    pP[rem * (Dd / 2) + d2] = make_uint2(hi, lo);
}

// ---------------- split a fp32 weight into interleaved format ----------------
__global__ void split_w(const float* __restrict__ src, uint2* __restrict__ dst, long n4) {
    long i = (long)blockIdx.x * blockDim.x + threadIdx.x;
    if (i >= n4) return;
    float4 v = *(const float4*)(src + i * 4);
    ((uint4*)dst)[i] = split_quad_i(v);
}

// ---------------- zero two buffers ----------------
__global__ void zero2(float* a, float* b, int n) {
    int i = blockIdx.x * blockDim.x + threadIdx.x;
    if (i < n) { a[i] = 0.f; b[i] = 0.f; }
}

// ---------------- tensor-core batched GEMM (interleaved split, 3 passes) ----------------
// mode 0: write relu output interleaved (cP)
// mode 1: fused mean-pool via atomicAdd into pool[sample][col]
#define BM 128
#define BN 64
#define BK 16
#define APITCH 24
#define BPITCH 72
#define A_PLANE (BM*APITCH)
#define B_PLANE (BK*BPITCH)

__global__ void __launch_bounds__(256, 2) mma_gemm2(
    const uint2* __restrict__ aP, long aStrideP,
    const uint2* __restrict__ wP, long wStrideP,
    const float* __restrict__ bias, long biasStride,
    uint2* cP, long cStrideP,
    float* pool,
    int M, int N, int K, int mode)
{
    int bz = blockIdx.z;
    aP   += (long)bz * aStrideP;
    wP   += (long)bz * wStrideP;
    bias += (long)bz * biasStride;

    __shared__ __nv_bfloat16 sA[2][2][A_PLANE];
    __shared__ __nv_bfloat16 sB[2][2][B_PLANE];

    int m0 = blockIdx.x * BM;
    int n0 = blockIdx.y * BN;
    int tid  = threadIdx.x;
    int lane = tid & 31;
    int warp = tid >> 5;
    int wm = warp & 3;
    int wn = warp >> 2;

    unsigned aBase = (unsigned)__cvta_generic_to_shared(&sA[0][0][0]);
    unsigned bBase = (unsigned)__cvta_generic_to_shared(&sB[0][0][0]);
    // A frags: lanes 0-15 rows, 16-31 col+8
    unsigned aAddr[2];
    #pragma unroll
    for (int mt = 0; mt < 2; mt++)
        aAddr[mt] = aBase + (unsigned)(((wm * 32 + mt * 16 + (lane & 15)) * APITCH + (lane >> 4) * 8) * 2);
    // B frags (x4 trans): mat = lane>>3: {k0-7,c}, {k8-15,c}, {k0-7,c+8}, {k8-15,c+8}
    unsigned bAddr[2];
    {
        int krow = (lane & 7) + ((lane >> 3) & 1) * 8;
        int cofs = (lane >> 4) * 8;
        #pragma unroll
        for (int ntp = 0; ntp < 2; ntp++)
            bAddr[ntp] = bBase + (unsigned)((krow * BPITCH + wn * 32 + ntp * 16 + cofs) * 2);
    }

    const unsigned A_PLANE_B = A_PLANE * 2;
    const unsigned A_BUF_B   = 2 * A_PLANE_B;
    const unsigned B_PLANE_B = B_PLANE * 2;
    const unsigned B_BUF_B   = 2 * B_PLANE_B;

    uint4 aPack[2], bPack;
    int ntile = K / BK;
    const int K2 = K / 2, N2 = N / 2;

    auto loadTile = [&](int t) {
        int k0 = t * BK;
        #pragma unroll
        for (int i = 0; i < 2; i++) {
            int idx = tid + i * 256;
            int row = idx >> 2, kq = idx & 3;
            int gm = m0 + row;
            if (gm < M) aPack[i] = *(const uint4*)(aP + (long)gm * K2 + (k0 >> 1) + kq * 2);
            else        aPack[i] = make_uint4(0u, 0u, 0u, 0u);
        }
        {
            int krow = tid >> 4, nq = tid & 15;
            bPack = *(const uint4*)(wP + (long)(k0 + krow) * N2 + (n0 >> 1) + nq * 2);
        }
    };
    auto storeTile = [&](int buf) {
        #pragma unroll
        for (int i = 0; i < 2; i++) {
            int idx = tid + i * 256;
            int row = idx >> 2, kq = idx & 3;
            int e = row * APITCH + kq * 4;
            *(uint2*)(&sA[buf][0][e]) = make_uint2(aPack[i].x, aPack[i].z);
            *(uint2*)(&sA[buf][1][e]) = make_uint2(aPack[i].y, aPack[i].w);
        }
        {
            int krow = tid >> 4, nq = tid & 15;
            int e = krow * BPITCH + nq * 4;
            *(uint2*)(&sB[buf][0][e]) = make_uint2(bPack.x, bPack.z);
            *(uint2*)(&sB[buf][1][e]) = make_uint2(bPack.y, bPack.w);
        }
    };

    float acc[2][4][4];
    #pragma unroll
    for (int i = 0; i < 2; i++)
        #pragma unroll
        for (int j = 0; j < 4; j++)
            #pragma unroll
            for (int k = 0; k < 4; k++) acc[i][j][k] = 0.f;

    loadTile(0);
    storeTile(0);
    if (ntile > 1) loadTile(1);
    __syncthreads();

    for (int t = 0; t < ntile; t++) {
        int cur = t & 1;
        if (t + 1 < ntile) {
            storeTile((t + 1) & 1);
            if (t + 2 < ntile) loadTile(t + 2);
        }
        unsigned aOff = (unsigned)cur * A_BUF_B;
        unsigned bOff = (unsigned)cur * B_BUF_B;

        unsigned afr[2][2][4];
        #pragma unroll
        for (int mt = 0; mt < 2; mt++) {
            ldsm_x4(afr[0][mt], aAddr[mt] + aOff);
            ldsm_x4(afr[1][mt], aAddr[mt] + aOff + A_PLANE_B);
        }
        unsigned bfr[2][2][4];   // [plane][ntp][4] -> nt=2*ntp uses [0..1], nt=2*ntp+1 uses [2..3]
        #pragma unroll
        for (int ntp = 0; ntp < 2; ntp++) {
            ldsm_x4t(bfr[0][ntp], bAddr[ntp] + bOff);
            ldsm_x4t(bfr[1][ntp], bAddr[ntp] + bOff + B_PLANE_B);
        }
        #pragma unroll
        for (int mt = 0; mt < 2; mt++)
            #pragma unroll
            for (int nt = 0; nt < 4; nt++) {
                const unsigned* b0 = &bfr[0][nt >> 1][(nt & 1) * 2];
                const unsigned* b1 = &bfr[1][nt >> 1][(nt & 1) * 2];
                mma_bf16(acc[mt][nt], afr[0][mt], b0);  // hi*hi
                mma_bf16(acc[mt][nt], afr[1][mt], b0);  // lo*hi
                mma_bf16(acc[mt][nt], afr[0][mt], b1);  // hi*lo
            }
        __syncthreads();
    }

    int g  = lane >> 2;
    int c4 = lane & 3;

    if (mode == 0) {
        cP += (long)bz * cStrideP;
        #pragma unroll
        for (int mt = 0; mt < 2; mt++) {
            int r0 = m0 + wm * 32 + mt * 16 + g;
            #pragma unroll
            for (int nt = 0; nt < 4; nt++) {
                int col = n0 + wn * 32 + nt * 8 + 2 * c4;
                float bx = bias[col], by = bias[col + 1];
                if (r0 < M) {
                    float v0 = fmaxf(acc[mt][nt][0] + bx, 0.f);
                    float v1 = fmaxf(acc[mt][nt][1] + by, 0.f);
                    unsigned hi, lo;
                    split_pair(v0, v1, hi, lo);
                    cP[(long)r0 * N2 + (col >> 1)] = make_uint2(hi, lo);
                }
                if (r0 + 8 < M) {
                    float v0 = fmaxf(acc[mt][nt][2] + bx, 0.f);
                    float v1 = fmaxf(acc[mt][nt][3] + by, 0.f);
                    unsigned hi, lo;
                    split_pair(v0, v1, hi, lo);
                    cP[(long)(r0 + 8) * N2 + (col >> 1)] = make_uint2(hi, lo);
                }
            }
        }
    } else {
        int warpRow0 = m0 + wm * 32;
        if (warpRow0 < M) {
            int sLocal = warpRow0 / Pp;
            int sampA  = bz + sLocal;
            int bnd    = (sLocal + 1) * Pp - warpRow0;
            bool has2  = (bnd < 32) && (warpRow0 + bnd) < M;
            float t0[8], t1[8];
            #pragma unroll
            for (int s = 0; s < 8; s++) { t0[s] = 0.f; t1[s] = 0.f; }
            #pragma unroll
            for (int mt = 0; mt < 2; mt++) {
                int lr0 = mt * 16 + g;
                int lr1 = lr0 + 8;
                bool ok0 = (warpRow0 + lr0) < M;
                bool ok1 = (warpRow0 + lr1) < M;
                #pragma unroll
                for (int nt = 0; nt < 4; nt++) {
                    int col = n0 + wn * 32 + nt * 8 + 2 * c4;
                    float bx = bias[col], by = bias[col + 1];
                    float a0 = fmaxf(acc[mt][nt][0] + bx, 0.f);
                    float a1 = fmaxf(acc[mt][nt][1] + by, 0.f);
                    float a2 = fmaxf(acc[mt][nt][2] + bx, 0.f);
                    float a3 = fmaxf(acc[mt][nt][3] + by, 0.f);
                    int s0 = nt * 2, s1 = nt * 2 + 1;
                    if (ok0) {
                        if (lr0 < bnd) { t0[s0] += a0; t0[s1] += a1; }
                        else           { t1[s0] += a0; t1[s1] += a1; }
                    }
                    if (ok1) {
                        if (lr1 < bnd) { t0[s0] += a2; t0[s1] += a3; }
                        else           { t1[s0] += a2; t1[s1] += a3; }
                    }
                }
            }
            #pragma unroll
            for (int ofs = 4; ofs < 32; ofs <<= 1) {
                #pragma unroll
                for (int s = 0; s < 8; s++)
                    t0[s] += __shfl_xor_sync(0xFFFFFFFFu, t0[s], ofs);
            }
            if (has2) {
                #pragma unroll
                for (int ofs = 4; ofs < 32; ofs <<= 1) {
                    #pragma unroll
                    for (int s = 0; s < 8; s++)
                        t1[s] += __shfl_xor_sync(0xFFFFFFFFu, t1[s], ofs);
                }
            }
            if (lane < 4) {
                const float inv = 1.f / (float)Pp;
                #pragma unroll
                for (int nt = 0; nt < 4; nt++) {
                    #pragma unroll
                    for (int cp = 0; cp < 2; cp++) {
                        int col = n0 + wn * 32 + nt * 8 + 2 * lane + cp;
                        atomicAdd(&pool[(long)sampA * N + col], t0[nt * 2 + cp] * inv);
                        if (has2)
                            atomicAdd(&pool[(long)(sampA + 1) * N + col], t1[nt * 2 + cp] * inv);
                    }
                }
            }
        }
    }
}

// ---------------- small-M GEMM with in-block split-K ----------------
__global__ void rowgemm_kernel(const float* __restrict__ A,
                               const float* __restrict__ W, long wStride,
                               const float* __restrict__ bias, long biasStride,
                               float* __restrict__ C, int N, int K)
{
    int b  = blockIdx.x;
    int nl = threadIdx.x & 31;
    int kg = threadIdx.x >> 5;
    int n  = blockIdx.y * 32 + nl;
    const float* a = A + (long)b * K;
    const float* w = W + (long)b * wStride;
    int kchunk = K / 8;
    float acc = 0.f;
    for (int k = kg * kchunk; k < (kg + 1) * kchunk; k++)
        acc = fmaf(a[k], w[(long)k * N + n], acc);
    __shared__ float red[8][32];
    red[kg][nl] = acc;
    __syncthreads();
    if (kg == 0) {
        float s = acc;
        #pragma unroll
        for (int j = 1; j < 8; j++) s += red[j][nl];
        C[(long)b * N + n] = s + bias[(long)b * biasStride + n];
    }
}

// ---------------- MetaNet ----------------
__global__ void meta_kernel(const float* __restrict__ base,
                            const float* __restrict__ mW1, const float* __restrict__ mb1,
                            const float* __restrict__ mW2, const float* __restrict__ mb2,
                            float* __restrict__ coef)
{
    int b = blockIdx.x;
    __shared__ float br[Ff];
    __shared__ float hid[MHh];
    int t = threadIdx.x;
    for (int i = t; i < Ff; i += MHh) br[i] = base[b * Ff + i];
    __syncthreads();
    float acc = mb1[t];
    for (int e = 0; e < Ff; e++) acc = fmaf(br[e], mW1[e * MHh + t], acc);
    hid[t] = fmaxf(acc, 0.f);
    __syncthreads();
    if (t < Tn) {
        float c = mb2[t];
        for (int j = 0; j < MHh; j++) c = fmaf(hid[j], mW2[j * Tn + t], c);
        coef[b * Tn + t] = c;
    }
}

// ---------------- compose biases (fp32) ----------------
__global__ void compose_kernel(const float* __restrict__ W, const float* __restrict__ dW,
                               const float* __restrict__ coef, float* __restrict__ out, long S)
{
    __shared__ float cs[Bn * Tn];
    if (threadIdx.x < Bn * Tn) cs[threadIdx.x] = coef[threadIdx.x];
    __syncthreads();
    long i = (long)blockIdx.x * blockDim.x + threadIdx.x;
    if (i >= S) return;
    float w = W[i];
    float d[Tn];
    #pragma unroll
    for (int t = 0; t < Tn; t++) d[t] = dW[(long)t * S + i];
    #pragma unroll 4
    for (int b = 0; b < Bn; b++) {
        float v = w;
        #pragma unroll
        for (int t = 0; t < Tn; t++) v = fmaf(cs[b * Tn + t], d[t], v);
        out[(long)b * S + i] = v;
    }
}

// ---------------- compose weights -> interleaved split ----------------
__global__ void compose_split(const float* __restrict__ W, const float* __restrict__ dW,
                              const float* __restrict__ coef, uint2* __restrict__ oP, long S)
{
    __shared__ float cs[Bn * Tn];
    if (threadIdx.x < Bn * Tn) cs[threadIdx.x] = coef[threadIdx.x];
    __syncthreads();
    long q = (long)blockIdx.x * blockDim.x + threadIdx.x;
    if (q >= S / 4) return;
    long e = q * 4;
    float4 w = *(const float4*)(W + e);
    float4 d[Tn];
    #pragma unroll
    for (int t = 0; t < Tn; t++) d[t] = *(const float4*)(dW + (long)t * S + e);
    for (int b = 0; b < Bn; b++) {
        float4 v = w;
        #pragma unroll
        for (int t = 0; t < Tn; t++) {
            float c = cs[b * Tn + t];
            v.x = fmaf(c, d[t].x, v.x);
            v.y = fmaf(c, d[t].y, v.y);
            v.z = fmaf(c, d[t].z, v.z);
            v.w = fmaf(c, d[t].w, v.w);
        }
        ((uint4*)oP)[((long)b * S + e) >> 2] = split_quad_i(v);
    }
}

// ---------------- y[t,b,n] = h2m[b,:] @ dW3[t,:,n] ----------------
#define YNC 16
__global__ void ydw3_kernel(const float* __restrict__ h2m, const float* __restrict__ dW3,
                            float* __restrict__ y)
{
    int t  = blockIdx.y;
    int n0 = blockIdx.x * YNC;
    const float* w = dW3 + (long)t * DHh * Ff;
    __shared__ float sw[16][YNC];
    __shared__ float sh[Bn][16];
    int tid = threadIdx.x;
    int b  = tid >> 3;
    int nl = tid & 7;
    float acc0 = 0.f, acc1 = 0.f;
    for (int k0 = 0; k0 < DHh; k0 += 16) {
        if (tid < 64) {
            int kk = tid >> 2, nq = tid & 3;
            float4 v = *(const float4*)(w + (long)(k0 + kk) * Ff + n0 + nq * 4);
            sw[kk][nq * 4 + 0] = v.x; sw[kk][nq * 4 + 1] = v.y;
            sw[kk][nq * 4 + 2] = v.z; sw[kk][nq * 4 + 3] = v.w;
        }
        if (tid >= 128) {
            int tt = tid - 128;
            int bb = tt >> 2, kq = tt & 3;
            float4 v = *(const float4*)(h2m + (long)bb * DHh + k0 + kq * 4);
            sh[bb][kq * 4 + 0] = v.x; sh[bb][kq * 4 + 1] = v.y;
            sh[bb][kq * 4 + 2] = v.z; sh[bb][kq * 4 + 3] = v.w;
        }
        __syncthreads();
        #pragma unroll
        for (int kk = 0; kk < 16; kk++) {
            float a = sh[b][kk];
            acc0 = fmaf(a, sw[kk][nl * 2 + 0], acc0);
            acc1 = fmaf(a, sw[kk][nl * 2 + 1], acc1);
        }
        __syncthreads();
    }
    long o = ((long)t * Bn + b) * Ff + n0 + nl * 2;
    y[o]     = acc0;
    y[o + 1] = acc1;
}

// ---------------- final combine ----------------
__global__ void combine_kernel(const float* __restrict__ z0, const float* __restrict__ y,
                               const float* __restrict__ coef, const float* __restrict__ db3,
                               float* __restrict__ out)
{
    int i = blockIdx.x * blockDim.x + threadIdx.x;
    if (i >= Bn * Ff) return;
    int b = i / Ff, n = i % Ff;
    float v = z0[i];
    #pragma unroll
    for (int t = 0; t < Tn; t++)
        v = fmaf(coef[b * Tn + t], y[((long)t * Bn + b) * Ff + n] + db3[t * Ff + n], v);
    out[i] = v;
}

// ---------------- launch ----------------
extern "C" void kernel_launch(void* const* d_in, const int* in_sizes, int n_in,
                              void* d_out, int out_size)
{
    const float* x   = (const float*)d_in[0];
    const float* W1  = (const float*)d_in[1];
    const float* b1  = (const float*)d_in[2];
    const float* W2  = (const float*)d_in[3];
    const float* b2  = (const float*)d_in[4];
    const float* W3  = (const float*)d_in[5];
    const float* b3  = (const float*)d_in[6];
    const float* dW1 = (const float*)d_in[7];
    const float* db1 = (const float*)d_in[8];
    const float* dW2 = (const float*)d_in[9];
    const float* db2 = (const float*)d_in[10];
    const float* dW3 = (const float*)d_in[11];
    const float* db3 = (const float*)d_in[12];
    const float* mW1 = (const float*)d_in[13];
    const float* mb1 = (const float*)d_in[14];
    const float* mW2 = (const float*)d_in[15];
    const float* mb2 = (const float*)d_in[16];
    float* out = (float*)d_out;

    uint2 *pP, *hP, *hbP, *W1sP, *W2sP, *W1bP, *W2bP;
    float *h2m0, *h2m1, *base, *coef, *b1b, *b2b, *z0, *y;
    cudaGetSymbolAddress((void**)&pP,   g_pP);
    cudaGetSymbolAddress((void**)&hP,   g_hP);
    cudaGetSymbolAddress((void**)&hbP,  g_hbP);
    cudaGetSymbolAddress((void**)&W1sP, g_W1sP);
    cudaGetSymbolAddress((void**)&W2sP, g_W2sP);
    cudaGetSymbolAddress((void**)&W1bP, g_W1bP);
    cudaGetSymbolAddress((void**)&W2bP, g_W2bP);
    cudaGetSymbolAddress((void**)&h2m0, g_h2m0);
    cudaGetSymbolAddress((void**)&h2m1, g_h2m1);
    cudaGetSymbolAddress((void**)&base, g_base);
    cudaGetSymbolAddress((void**)&coef, g_coef);
    cudaGetSymbolAddress((void**)&b1b,  g_b1b);
    cudaGetSymbolAddress((void**)&b2b,  g_b2b);
    cudaGetSymbolAddress((void**)&z0,   g_z0);
    cudaGetSymbolAddress((void**)&y,    g_y);

    // 1) patchify -> interleaved split
    {
        long n = (long)BP * Dd / 2;
        patchify_split<<<(unsigned)((n + 255) / 256), 256>>>(x, pP);
    }
    // 2) pre-split base weights
    split_w<<<(unsigned)(((long)Dd * Dd / 4 + 255) / 256), 256>>>(W1, W1sP, (long)Dd * Dd / 4);
    split_w<<<(unsigned)(((long)Dd * DHh / 4 + 255) / 256), 256>>>(W2, W2sP, (long)Dd * DHh / 4);
    // 3) zero pool accumulators
    zero2<<<(Bn * DHh + 255) / 256, 256>>>(h2m0, h2m1, Bn * DHh);

    // 4) base layer1: h = relu(p @ W1 + b1)
    mma_gemm2<<<dim3(BP / BM, Dd / BN, 1), 256>>>(
        pP, 0, W1sP, 0, b1, 0,
        hP, 0, nullptr, BP, Dd, Dd, 0);

    // 5) base layer2 + fused mean-pool -> h2m0
    mma_gemm2<<<dim3(BP / BM, DHh / BN, 1), 256>>>(
        hP, 0, W2sP, 0, b2, 0,
        nullptr, 0, h2m0, BP, DHh, Dd, 1);

    // 6) base = h2m0 @ W3 + b3
    rowgemm_kernel<<<dim3(Bn, Ff / 32), 256>>>(h2m0, W3, 0, b3, 0, base, Ff, DHh);

    // 7) MetaNet -> coefs
    meta_kernel<<<Bn, MHh>>>(base, mW1, mb1, mW2, mb2, coef);

    // 8) compose biases + weights (interleaved)
    compose_kernel<<<(Dd  + 255) / 256, 256>>>(b1, db1, coef, b1b, Dd);
    compose_kernel<<<(DHh + 255) / 256, 256>>>(b2, db2, coef, b2b, DHh);
    {
        long S1 = (long)Dd * Dd;
        long S2 = (long)Dd * DHh;
        compose_split<<<(unsigned)((S1 / 4 + 255) / 256), 256>>>(W1, dW1, coef, W1bP, S1);
        compose_split<<<(unsigned)((S2 / 4 + 255) / 256), 256>>>(W2, dW2, coef, W2bP, S2);
    }

    // 9) adapted layer1 (batched): hb = relu(p @ W1b + b1b)
    mma_gemm2<<<dim3((Pp + BM - 1) / BM, Dd / BN, Bn), 256>>>(
        pP,   (long)Pp * Dd / 2,
        W1bP, (long)Dd * Dd / 2,
        b1b,  (long)Dd,
        hbP,  (long)Pp * Dd / 2, nullptr,
        Pp, Dd, Dd, 0);

    // 10) adapted layer2 + fused mean-pool -> h2m1
    mma_gemm2<<<dim3((Pp + BM - 1) / BM, DHh / BN, Bn), 256>>>(
        hbP,  (long)Pp * Dd / 2,
        W2bP, (long)Dd * DHh / 2,
        b2b,  (long)DHh,
        nullptr, 0, h2m1,
        Pp, DHh, Dd, 1);

    // 11) z0 = h2m1 @ W3 + b3
    rowgemm_kernel<<<dim3(Bn, Ff / 32), 256>>>(h2m1, W3, 0, b3, 0, z0, Ff, DHh);

    // 12) y[t,b,:] = h2m1[b,:] @ dW3[t]
    ydw3_kernel<<<dim3(Ff / YNC, Tn), 256>>>(h2m1, dW3, y);

    // 13) out = z0 + sum_t coef*(y + db3)
    combine_kernel<<<(Bn * Ff + 255) / 256, 256>>>(z0, y, coef, db3, out);
}

// round 6
// speedup vs baseline: 1.5596x; 1.3785x over previous
#include <cuda_runtime.h>
#include <cuda_fp16.h>

// ---------------- problem constants ----------------
#define Bn   32
#define Tn   8
#define Dd   768
#define DHh  3072
#define Ff   512
#define MHh  128
#define Pp   196
#define BP   (Bn*Pp)

// ---------------- device scratch (fp16 single precision-pass) ----------------
__device__ __half g_pH  [(long)BP*Dd];
__device__ __half g_hH  [(long)BP*Dd];
__device__ __half g_hbH [(long)BP*Dd];
__device__ __half g_W1sH[(long)Dd*Dd];
__device__ __half g_W2sH[(long)Dd*DHh];
__device__ __half g_W1bH[(long)Bn*Dd*Dd];
__device__ __half g_W2bH[(long)Bn*Dd*DHh];
__device__ float g_h2m0[Bn*DHh], g_h2m1[Bn*DHh];
__device__ float g_base[Bn*Ff],  g_coef[Bn*Tn];
__device__ float g_b1b[Bn*Dd],   g_b2b[Bn*DHh];
__device__ float g_z0[Bn*Ff],    g_y[(long)Tn*Bn*Ff];

// ---------------- helpers ----------------
__device__ __forceinline__ unsigned pack_h2(float a, float b) {
    __half2 h = __floats2half2_rn(a, b);
    return *reinterpret_cast<unsigned*>(&h);
}

__device__ __forceinline__ void mma_f16(float* c, const unsigned* a, const unsigned* b) {
    asm volatile(
        "mma.sync.aligned.m16n8k16.row.col.f32.f16.f16.f32 "
        "{%0,%1,%2,%3}, {%4,%5,%6,%7}, {%8,%9}, {%0,%1,%2,%3};"
        : "+f"(c[0]), "+f"(c[1]), "+f"(c[2]), "+f"(c[3])
        : "r"(a[0]), "r"(a[1]), "r"(a[2]), "r"(a[3]), "r"(b[0]), "r"(b[1]));
}
__device__ __forceinline__ void ldsm_x4(unsigned* r, unsigned addr) {
    asm volatile("ldmatrix.sync.aligned.m8n8.x4.shared.b16 {%0,%1,%2,%3}, [%4];"
                 : "=r"(r[0]), "=r"(r[1]), "=r"(r[2]), "=r"(r[3]) : "r"(addr));
}
__device__ __forceinline__ void ldsm_x4t(unsigned* r, unsigned addr) {
    asm volatile("ldmatrix.sync.aligned.m8n8.x4.trans.shared.b16 {%0,%1,%2,%3}, [%4];"
                 : "=r"(r[0]), "=r"(r[1]), "=r"(r[2]), "=r"(r[3]) : "r"(addr));
}

// ---------------- patchify: x -> fp16 ----------------
__global__ void patchify_h(const float* __restrict__ x, __half* __restrict__ p) {
    long q = (long)blockIdx.x * blockDim.x + threadIdx.x;
    if (q >= (long)BP * Dd / 2) return;
    int d2   = (int)(q % (Dd / 2));
    long rem = q / (Dd / 2);
    int patch = (int)(rem % Pp);
    int b     = (int)(rem / Pp);
    int d  = d2 * 2;
    int pi = patch / 14, pj = patch % 14;
    int c = d >> 8, r = (d >> 4) & 15, s = d & 15;
    float2 v = *(const float2*)(x + ((long)(b * 3 + c) * 224 + pi * 16 + r) * 224 + pj * 16 + s);
    *(unsigned*)(p + rem * Dd + d) = pack_h2(v.x, v.y);
}

// ---------------- convert fp32 weight -> fp16 ----------------
__global__ void cvt_w(const float* __restrict__ src, __half* __restrict__ dst, long n4) {
    long i = (long)blockIdx.x * blockDim.x + threadIdx.x;
    if (i >= n4) return;
    float4 v = *(const float4*)(src + i * 4);
    uint2 o = make_uint2(pack_h2(v.x, v.y), pack_h2(v.z, v.w));
    *(uint2*)(dst + i * 4) = o;
}

// ---------------- zero two buffers ----------------
__global__ void zero2(float* a, float* b, int n) {
    int i = blockIdx.x * blockDim.x + threadIdx.x;
    if (i < n) { a[i] = 0.f; b[i] = 0.f; }
}

// ---------------- tensor-core batched GEMM (fp16 single pass) ----------------
// mode 0: write relu output fp16 (cH)
// mode 1: fused mean-pool via atomicAdd into pool[sample][col]
#define BM 128
#define BN 64
#define BK 16
#define APITCH 24   // halves per A smem row (16 data + 8 pad) = 48B
#define BPITCH 72   // halves per B smem row (64 data + 8 pad) = 144B
#define A_PLANE (BM*APITCH)
#define B_PLANE (BK*BPITCH)

__global__ void __launch_bounds__(256) mma_gemm3(
    const __half* __restrict__ aH, long aStride,
    const __half* __restrict__ wH, long wStride,
    const float* __restrict__ bias, long biasStride,
    __half* cH, long cStride,
    float* pool,
    int M, int N, int K, int mode)
{
    int bz = blockIdx.z;
    aH   += (long)bz * aStride;
    wH   += (long)bz * wStride;
    bias += (long)bz * biasStride;

    __shared__ __half sA[2][A_PLANE];
    __shared__ __half sB[2][B_PLANE];

    int m0 = blockIdx.x * BM;
    int n0 = blockIdx.y * BN;
    int tid  = threadIdx.x;
    int lane = tid & 31;
    int warp = tid >> 5;
    int wm = warp & 3;
    int wn = warp >> 2;

    unsigned aBase = (unsigned)__cvta_generic_to_shared(&sA[0][0]);
    unsigned bBase = (unsigned)__cvta_generic_to_shared(&sB[0][0]);
    unsigned aAddr[2];
    #pragma unroll
    for (int mt = 0; mt < 2; mt++)
        aAddr[mt] = aBase + (unsigned)(((wm * 32 + mt * 16 + (lane & 15)) * APITCH + (lane >> 4) * 8) * 2);
    unsigned bAddr[2];
    {
        int krow = (lane & 7) + ((lane >> 3) & 1) * 8;
        int cofs = (lane >> 4) * 8;
        #pragma unroll
        for (int ntp = 0; ntp < 2; ntp++)
            bAddr[ntp] = bBase + (unsigned)((krow * BPITCH + wn * 32 + ntp * 16 + cofs) * 2);
    }

    const unsigned A_BUF_B = A_PLANE * 2;
    const unsigned B_BUF_B = B_PLANE * 2;

    uint4 aPack;   // 8 halves
    uint2 bPack;   // 4 halves
    int ntile = K / BK;

    // A: thread -> row = tid>>1, 8-half chunk (tid&1); B: row = tid>>4, 4-half chunk
    int aRow = tid >> 1, aKq = tid & 1;
    int bKrow = tid >> 4, bNq = tid & 15;

    auto loadTile = [&](int t) {
        int k0 = t * BK;
        int gm = m0 + aRow;
        if (gm < M) aPack = *(const uint4*)(aH + (long)gm * K + k0 + aKq * 8);
        else        aPack = make_uint4(0u, 0u, 0u, 0u);
        bPack = *(const uint2*)(wH + (long)(k0 + bKrow) * N + n0 + bNq * 4);
    };
    auto storeTile = [&](int buf) {
        *(uint4*)(&sA[buf][aRow * APITCH + aKq * 8]) = aPack;
        *(uint2*)(&sB[buf][bKrow * BPITCH + bNq * 4]) = bPack;
    };

    float acc[2][4][4];
    #pragma unroll
    for (int i = 0; i < 2; i++)
        #pragma unroll
        for (int j = 0; j < 4; j++)
            #pragma unroll
            for (int k = 0; k < 4; k++) acc[i][j][k] = 0.f;

    loadTile(0);
    storeTile(0);
    if (ntile > 1) loadTile(1);
    __syncthreads();

    for (int t = 0; t < ntile; t++) {
        int cur = t & 1;
        if (t + 1 < ntile) {
            storeTile((t + 1) & 1);
            if (t + 2 < ntile) loadTile(t + 2);
        }
        unsigned aOff = (unsigned)cur * A_BUF_B;
        unsigned bOff = (unsigned)cur * B_BUF_B;

        unsigned afr[2][4];
        #pragma unroll
        for (int mt = 0; mt < 2; mt++)
            ldsm_x4(afr[mt], aAddr[mt] + aOff);
        unsigned bfr[2][4];   // [ntp][4]: nt=2*ntp -> [0..1], nt=2*ntp+1 -> [2..3]
        #pragma unroll
        for (int ntp = 0; ntp < 2; ntp++)
            ldsm_x4t(bfr[ntp], bAddr[ntp] + bOff);
        #pragma unroll
        for (int mt = 0; mt < 2; mt++)
            #pragma unroll
            for (int nt = 0; nt < 4; nt++)
                mma_f16(acc[mt][nt], afr[mt], &bfr[nt >> 1][(nt & 1) * 2]);
        __syncthreads();
    }

    int g  = lane >> 2;
    int c4 = lane & 3;

    if (mode == 0) {
        cH += (long)bz * cStride;
        #pragma unroll
        for (int mt = 0; mt < 2; mt++) {
            int r0 = m0 + wm * 32 + mt * 16 + g;
            #pragma unroll
            for (int nt = 0; nt < 4; nt++) {
                int col = n0 + wn * 32 + nt * 8 + 2 * c4;
                float bx = bias[col], by = bias[col + 1];
                if (r0 < M) {
                    float v0 = fmaxf(acc[mt][nt][0] + bx, 0.f);
                    float v1 = fmaxf(acc[mt][nt][1] + by, 0.f);
                    *(unsigned*)(cH + (long)r0 * N + col) = pack_h2(v0, v1);
                }
                if (r0 + 8 < M) {
                    float v0 = fmaxf(acc[mt][nt][2] + bx, 0.f);
                    float v1 = fmaxf(acc[mt][nt][3] + by, 0.f);
                    *(unsigned*)(cH + (long)(r0 + 8) * N + col) = pack_h2(v0, v1);
                }
            }
        }
    } else {
        int warpRow0 = m0 + wm * 32;
        if (warpRow0 < M) {
            int sLocal = warpRow0 / Pp;
            int sampA  = bz + sLocal;
            int bnd    = (sLocal + 1) * Pp - warpRow0;
            bool has2  = (bnd < 32) && (warpRow0 + bnd) < M;
            float t0[8], t1[8];
            #pragma unroll
            for (int s = 0; s < 8; s++) { t0[s] = 0.f; t1[s] = 0.f; }
            #pragma unroll
            for (int mt = 0; mt < 2; mt++) {
                int lr0 = mt * 16 + g;
                int lr1 = lr0 + 8;
                bool ok0 = (warpRow0 + lr0) < M;
                bool ok1 = (warpRow0 + lr1) < M;
                #pragma unroll
                for (int nt = 0; nt < 4; nt++) {
                    int col = n0 + wn * 32 + nt * 8 + 2 * c4;
                    float bx = bias[col], by = bias[col + 1];
                    float a0 = fmaxf(acc[mt][nt][0] + bx, 0.f);
                    float a1 = fmaxf(acc[mt][nt][1] + by, 0.f);
                    float a2 = fmaxf(acc[mt][nt][2] + bx, 0.f);
                    float a3 = fmaxf(acc[mt][nt][3] + by, 0.f);
                    int s0 = nt * 2, s1 = nt * 2 + 1;
                    if (ok0) {
                        if (lr0 < bnd) { t0[s0] += a0; t0[s1] += a1; }
                        else           { t1[s0] += a0; t1[s1] += a1; }
                    }
                    if (ok1) {
                        if (lr1 < bnd) { t0[s0] += a2; t0[s1] += a3; }
                        else           { t1[s0] += a2; t1[s1] += a3; }
                    }
                }
            }
            #pragma unroll
            for (int ofs = 4; ofs < 32; ofs <<= 1) {
                #pragma unroll
                for (int s = 0; s < 8; s++)
                    t0[s] += __shfl_xor_sync(0xFFFFFFFFu, t0[s], ofs);
            }
            if (has2) {
                #pragma unroll
                for (int ofs = 4; ofs < 32; ofs <<= 1) {
                    #pragma unroll
                    for (int s = 0; s < 8; s++)
                        t1[s] += __shfl_xor_sync(0xFFFFFFFFu, t1[s], ofs);
                }
            }
            if (lane < 4) {
                const float inv = 1.f / (float)Pp;
                #pragma unroll
                for (int nt = 0; nt < 4; nt++) {
                    #pragma unroll
                    for (int cp = 0; cp < 2; cp++) {
                        int col = n0 + wn * 32 + nt * 8 + 2 * lane + cp;
                        atomicAdd(&pool[(long)sampA * N + col], t0[nt * 2 + cp] * inv);
                        if (has2)
                            atomicAdd(&pool[(long)(sampA + 1) * N + col], t1[nt * 2 + cp] * inv);
                    }
                }
            }
        }
    }
}

// ---------------- small-M GEMM with in-block split-K ----------------
__global__ void rowgemm_kernel(const float* __restrict__ A,
                               const float* __restrict__ W, long wStride,
                               const float* __restrict__ bias, long biasStride,
                               float* __restrict__ C, int N, int K)
{
    int b  = blockIdx.x;
    int nl = threadIdx.x & 31;
    int kg = threadIdx.x >> 5;
    int n  = blockIdx.y * 32 + nl;
    const float* a = A + (long)b * K;
    const float* w = W + (long)b * wStride;
    int kchunk = K / 8;
    float acc = 0.f;
    for (int k = kg * kchunk; k < (kg + 1) * kchunk; k++)
        acc = fmaf(a[k], w[(long)k * N + n], acc);
    __shared__ float red[8][32];
    red[kg][nl] = acc;
    __syncthreads();
    if (kg == 0) {
        float s = acc;
        #pragma unroll
        for (int j = 1; j < 8; j++) s += red[j][nl];
        C[(long)b * N + n] = s + bias[(long)b * biasStride + n];
    }
}

// ---------------- MetaNet ----------------
__global__ void meta_kernel(const float* __restrict__ base,
                            const float* __restrict__ mW1, const float* __restrict__ mb1,
                            const float* __restrict__ mW2, const float* __restrict__ mb2,
                            float* __restrict__ coef)
{
    int b = blockIdx.x;
    __shared__ float br[Ff];
    __shared__ float hid[MHh];
    int t = threadIdx.x;
    for (int i = t; i < Ff; i += MHh) br[i] = base[b * Ff + i];
    __syncthreads();
    float acc = mb1[t];
    for (int e = 0; e < Ff; e++) acc = fmaf(br[e], mW1[e * MHh + t], acc);
    hid[t] = fmaxf(acc, 0.f);
    __syncthreads();
    if (t < Tn) {
        float c = mb2[t];
        for (int j = 0; j < MHh; j++) c = fmaf(hid[j], mW2[j * Tn + t], c);
        coef[b * Tn + t] = c;
    }
}

// ---------------- compose biases (fp32) ----------------
__global__ void compose_kernel(const float* __restrict__ W, const float* __restrict__ dW,
                               const float* __restrict__ coef, float* __restrict__ out, long S)
{
    __shared__ float cs[Bn * Tn];
    if (threadIdx.x < Bn * Tn) cs[threadIdx.x] = coef[threadIdx.x];
    __syncthreads();
    long i = (long)blockIdx.x * blockDim.x + threadIdx.x;
    if (i >= S) return;
    float w = W[i];
    float d[Tn];
    #pragma unroll
    for (int t = 0; t < Tn; t++) d[t] = dW[(long)t * S + i];
    #pragma unroll 4
    for (int b = 0; b < Bn; b++) {
        float v = w;
        #pragma unroll
        for (int t = 0; t < Tn; t++) v = fmaf(cs[b * Tn + t], d[t], v);
        out[(long)b * S + i] = v;
    }
}

// ---------------- compose weights -> fp16 ----------------
__global__ void compose_h(const float* __restrict__ W, const float* __restrict__ dW,
                          const float* __restrict__ coef, __half* __restrict__ oH, long S)
{
    __shared__ float cs[Bn * Tn];
    if (threadIdx.x < Bn * Tn) cs[threadIdx.x] = coef[threadIdx.x];
    __syncthreads();
    long q = (long)blockIdx.x * blockDim.x + threadIdx.x;
    if (q >= S / 4) return;
    long e = q * 4;
    float4 w = *(const float4*)(W + e);
    float4 d[Tn];
    #pragma unroll
    for (int t = 0; t < Tn; t++) d[t] = *(const float4*)(dW + (long)t * S + e);
    for (int b = 0; b < Bn; b++) {
        float4 v = w;
        #pragma unroll
        for (int t = 0; t < Tn; t++) {
            float c = cs[b * Tn + t];
            v.x = fmaf(c, d[t].x, v.x);
            v.y = fmaf(c, d[t].y, v.y);
            v.z = fmaf(c, d[t].z, v.z);
            v.w = fmaf(c, d[t].w, v.w);
        }
        *(uint2*)(oH + (long)b * S + e) = make_uint2(pack_h2(v.x, v.y), pack_h2(v.z, v.w));
    }
}

// ---------------- y[t,b,n] = h2m[b,:] @ dW3[t,:,n] ----------------
#define YNC 16
__global__ void ydw3_kernel(const float* __restrict__ h2m, const float* __restrict__ dW3,
                            float* __restrict__ y)
{
    int t  = blockIdx.y;
    int n0 = blockIdx.x * YNC;
    const float* w = dW3 + (long)t * DHh * Ff;
    __shared__ float sw[16][YNC];
    __shared__ float sh[Bn][16];
    int tid = threadIdx.x;
    int b  = tid >> 3;
    int nl = tid & 7;
    float acc0 = 0.f, acc1 = 0.f;
    for (int k0 = 0; k0 < DHh; k0 += 16) {
        if (tid < 64) {
            int kk = tid >> 2, nq = tid & 3;
            float4 v = *(const float4*)(w + (long)(k0 + kk) * Ff + n0 + nq * 4);
            sw[kk][nq * 4 + 0] = v.x; sw[kk][nq * 4 + 1] = v.y;
            sw[kk][nq * 4 + 2] = v.z; sw[kk][nq * 4 + 3] = v.w;
        }
        if (tid >= 128) {
            int tt = tid - 128;
            int bb = tt >> 2, kq = tt & 3;
            float4 v = *(const float4*)(h2m + (long)bb * DHh + k0 + kq * 4);
            sh[bb][kq * 4 + 0] = v.x; sh[bb][kq * 4 + 1] = v.y;
            sh[bb][kq * 4 + 2] = v.z; sh[bb][kq * 4 + 3] = v.w;
        }
        __syncthreads();
        #pragma unroll
        for (int kk = 0; kk < 16; kk++) {
            float a = sh[b][kk];
            acc0 = fmaf(a, sw[kk][nl * 2 + 0], acc0);
            acc1 = fmaf(a, sw[kk][nl * 2 + 1], acc1);
        }
        __syncthreads();
    }
    long o = ((long)t * Bn + b) * Ff + n0 + nl * 2;
    y[o]     = acc0;
    y[o + 1] = acc1;
}

// ---------------- final combine ----------------
__global__ void combine_kernel(const float* __restrict__ z0, const float* __restrict__ y,
                               const float* __restrict__ coef, const float* __restrict__ db3,
                               float* __restrict__ out)
{
    int i = blockIdx.x * blockDim.x + threadIdx.x;
    if (i >= Bn * Ff) return;
    int b = i / Ff, n = i % Ff;
    float v = z0[i];
    #pragma unroll
    for (int t = 0; t < Tn; t++)
        v = fmaf(coef[b * Tn + t], y[((long)t * Bn + b) * Ff + n] + db3[t * Ff + n], v);
    out[i] = v;
}

// ---------------- launch ----------------
extern "C" void kernel_launch(void* const* d_in, const int* in_sizes, int n_in,
                              void* d_out, int out_size)
{
    const float* x   = (const float*)d_in[0];
    const float* W1  = (const float*)d_in[1];
    const float* b1  = (const float*)d_in[2];
    const float* W2  = (const float*)d_in[3];
    const float* b2  = (const float*)d_in[4];
    const float* W3  = (const float*)d_in[5];
    const float* b3  = (const float*)d_in[6];
    const float* dW1 = (const float*)d_in[7];
    const float* db1 = (const float*)d_in[8];
    const float* dW2 = (const float*)d_in[9];
    const float* db2 = (const float*)d_in[10];
    const float* dW3 = (const float*)d_in[11];
    const float* db3 = (const float*)d_in[12];
    const float* mW1 = (const float*)d_in[13];
    const float* mb1 = (const float*)d_in[14];
    const float* mW2 = (const float*)d_in[15];
    const float* mb2 = (const float*)d_in[16];
    float* out = (float*)d_out;

    __half *pH, *hH, *hbH, *W1sH, *W2sH, *W1bH, *W2bH;
    float *h2m0, *h2m1, *base, *coef, *b1b, *b2b, *z0, *y;
    cudaGetSymbolAddress((void**)&pH,   g_pH);
    cudaGetSymbolAddress((void**)&hH,   g_hH);
    cudaGetSymbolAddress((void**)&hbH,  g_hbH);
    cudaGetSymbolAddress((void**)&W1sH, g_W1sH);
    cudaGetSymbolAddress((void**)&W2sH, g_W2sH);
    cudaGetSymbolAddress((void**)&W1bH, g_W1bH);
    cudaGetSymbolAddress((void**)&W2bH, g_W2bH);
    cudaGetSymbolAddress((void**)&h2m0, g_h2m0);
    cudaGetSymbolAddress((void**)&h2m1, g_h2m1);
    cudaGetSymbolAddress((void**)&base, g_base);
    cudaGetSymbolAddress((void**)&coef, g_coef);
    cudaGetSymbolAddress((void**)&b1b,  g_b1b);
    cudaGetSymbolAddress((void**)&b2b,  g_b2b);
    cudaGetSymbolAddress((void**)&z0,   g_z0);
    cudaGetSymbolAddress((void**)&y,    g_y);

    // 1) patchify -> fp16
    {
        long n = (long)BP * Dd / 2;
        patchify_h<<<(unsigned)((n + 255) / 256), 256>>>(x, pH);
    }
    // 2) convert base weights to fp16
    cvt_w<<<(unsigned)(((long)Dd * Dd / 4 + 255) / 256), 256>>>(W1, W1sH, (long)Dd * Dd / 4);
    cvt_w<<<(unsigned)(((long)Dd * DHh / 4 + 255) / 256), 256>>>(W2, W2sH, (long)Dd * DHh / 4);
    // 3) zero pool accumulators
    zero2<<<(Bn * DHh + 255) / 256, 256>>>(h2m0, h2m1, Bn * DHh);

    // 4) base layer1: h = relu(p @ W1 + b1)
    mma_gemm3<<<dim3(BP / BM, Dd / BN, 1), 256>>>(
        pH, 0, W1sH, 0, b1, 0,
        hH, 0, nullptr, BP, Dd, Dd, 0);

    // 5) base layer2 + fused mean-pool -> h2m0
    mma_gemm3<<<dim3(BP / BM, DHh / BN, 1), 256>>>(
        hH, 0, W2sH, 0, b2, 0,
        nullptr, 0, h2m0, BP, DHh, Dd, 1);

    // 6) base = h2m0 @ W3 + b3
    rowgemm_kernel<<<dim3(Bn, Ff / 32), 256>>>(h2m0, W3, 0, b3, 0, base, Ff, DHh);

    // 7) MetaNet -> coefs
    meta_kernel<<<Bn, MHh>>>(base, mW1, mb1, mW2, mb2, coef);

    // 8) compose biases + weights (fp16)
    compose_kernel<<<(Dd  + 255) / 256, 256>>>(b1, db1, coef, b1b, Dd);
    compose_kernel<<<(DHh + 255) / 256, 256>>>(b2, db2, coef, b2b, DHh);
    {
        long S1 = (long)Dd * Dd;
        long S2 = (long)Dd * DHh;
        compose_h<<<(unsigned)((S1 / 4 + 255) / 256), 256>>>(W1, dW1, coef, W1bH, S1);
        compose_h<<<(unsigned)((S2 / 4 + 255) / 256), 256>>>(W2, dW2, coef, W2bH, S2);
    }

    // 9) adapted layer1 (batched): hb = relu(p @ W1b + b1b)
    mma_gemm3<<<dim3((Pp + BM - 1) / BM, Dd / BN, Bn), 256>>>(
        pH,   (long)Pp * Dd,
        W1bH, (long)Dd * Dd,
        b1b,  (long)Dd,
        hbH,  (long)Pp * Dd, nullptr,
        Pp, Dd, Dd, 0);

    // 10) adapted layer2 + fused mean-pool -> h2m1
    mma_gemm3<<<dim3((Pp + BM - 1) / BM, DHh / BN, Bn), 256>>>(
        hbH,  (long)Pp * Dd,
        W2bH, (long)Dd * DHh,
        b2b,  (long)DHh,
        nullptr, 0, h2m1,
        Pp, DHh, Dd, 1);

    // 11) z0 = h2m1 @ W3 + b3
    rowgemm_kernel<<<dim3(Bn, Ff / 32), 256>>>(h2m1, W3, 0, b3, 0, z0, Ff, DHh);

    // 12) y[t,b,:] = h2m1[b,:] @ dW3[t]
    ydw3_kernel<<<dim3(Ff / YNC, Tn), 256>>>(h2m1, dW3, y);

    // 13) out = z0 + sum_t coef*(y + db3)
    combine_kernel<<<(Bn * Ff + 255) / 256, 256>>>(z0, y, coef, db3, out);
}

// round 7
// speedup vs baseline: 2.0559x; 1.3182x over previous
#include <cuda_runtime.h>
#include <cuda_fp16.h>

// ---------------- problem constants ----------------
#define Bn   32
#define Tn   8
#define Dd   768
#define DHh  3072
#define Ff   512
#define MHh  128
#define Pp   196
#define BP   (Bn*Pp)

// ---------------- device scratch (fp16 single pass) ----------------
__device__ __half g_pH  [(long)BP*Dd];
__device__ __half g_hH  [(long)BP*Dd];
__device__ __half g_hbH [(long)BP*Dd];
__device__ __half g_W1sH[(long)Dd*Dd];
__device__ __half g_W2sH[(long)Dd*DHh];
__device__ __half g_W1bH[(long)Bn*Dd*Dd];
__device__ __half g_W2bH[(long)Bn*Dd*DHh];
__device__ float g_h2m0[Bn*DHh], g_h2m1[Bn*DHh];
__device__ float g_base[Bn*Ff],  g_coef[Bn*Tn];
__device__ float g_b1b[Bn*Dd],   g_b2b[Bn*DHh];
__device__ float g_z0[Bn*Ff],    g_y[(long)Tn*Bn*Ff];

// ---------------- helpers ----------------
__device__ __forceinline__ unsigned pack_h2(float a, float b) {
    __half2 h = __floats2half2_rn(a, b);
    return *reinterpret_cast<unsigned*>(&h);
}
__device__ __forceinline__ void mma_f16(float* c, const unsigned* a, const unsigned* b) {
    asm volatile(
        "mma.sync.aligned.m16n8k16.row.col.f32.f16.f16.f32 "
        "{%0,%1,%2,%3}, {%4,%5,%6,%7}, {%8,%9}, {%0,%1,%2,%3};"
        : "+f"(c[0]), "+f"(c[1]), "+f"(c[2]), "+f"(c[3])
        : "r"(a[0]), "r"(a[1]), "r"(a[2]), "r"(a[3]), "r"(b[0]), "r"(b[1]));
}
__device__ __forceinline__ void ldsm_x4(unsigned* r, unsigned addr) {
    asm volatile("ldmatrix.sync.aligned.m8n8.x4.shared.b16 {%0,%1,%2,%3}, [%4];"
                 : "=r"(r[0]), "=r"(r[1]), "=r"(r[2]), "=r"(r[3]) : "r"(addr));
}
__device__ __forceinline__ void ldsm_x4t(unsigned* r, unsigned addr) {
    asm volatile("ldmatrix.sync.aligned.m8n8.x4.trans.shared.b16 {%0,%1,%2,%3}, [%4];"
                 : "=r"(r[0]), "=r"(r[1]), "=r"(r[2]), "=r"(r[3]) : "r"(addr));
}
__device__ __forceinline__ void cp16(unsigned smem, const void* g, int srcBytes) {
    asm volatile("cp.async.cg.shared.global [%0], [%1], 16, %2;"
                 :: "r"(smem), "l"(g), "r"(srcBytes));
}
#define CP_COMMIT() asm volatile("cp.async.commit_group;")
#define CP_WAIT1()  asm volatile("cp.async.wait_group 1;")

// ---------------- patchify: x -> fp16 ----------------
__global__ void patchify_h(const float* __restrict__ x, __half* __restrict__ p) {
    long q = (long)blockIdx.x * blockDim.x + threadIdx.x;
    if (q >= (long)BP * Dd / 2) return;
    int d2   = (int)(q % (Dd / 2));
    long rem = q / (Dd / 2);
    int patch = (int)(rem % Pp);
    int b     = (int)(rem / Pp);
    int d  = d2 * 2;
    int pi = patch / 14, pj = patch % 14;
    int c = d >> 8, r = (d >> 4) & 15, s = d & 15;
    float2 v = *(const float2*)(x + ((long)(b * 3 + c) * 224 + pi * 16 + r) * 224 + pj * 16 + s);
    *(unsigned*)(p + rem * Dd + d) = pack_h2(v.x, v.y);
}

// ---------------- convert fp32 weight -> fp16 ----------------
__global__ void cvt_w(const float* __restrict__ src, __half* __restrict__ dst, long n4) {
    long i = (long)blockIdx.x * blockDim.x + threadIdx.x;
    if (i >= n4) return;
    float4 v = *(const float4*)(src + i * 4);
    *(uint2*)(dst + i * 4) = make_uint2(pack_h2(v.x, v.y), pack_h2(v.z, v.w));
}

// ---------------- zero two buffers ----------------
__global__ void zero2(float* a, float* b, int n) {
    int i = blockIdx.x * blockDim.x + threadIdx.x;
    if (i < n) { a[i] = 0.f; b[i] = 0.f; }
}

// ---------------- tensor-core batched GEMM (fp16, 128x128x32, 3-stage cp.async) ----
#define BM 128
#define BN 128
#define BK 32
#define NSTAGE 3
#define APITCH 40    // halves per A row (32 data + 8 pad) = 80B
#define BPITCH 136   // halves per B row (128 data + 8 pad) = 272B
#define A_ST (BM*APITCH)            // halves per A stage
#define B_ST (BK*BPITCH)            // halves per B stage
#define STAGE_H (A_ST + B_ST)
#define SMEM_BYTES (NSTAGE*STAGE_H*2)

__global__ void __launch_bounds__(256) mma_gemm4(
    const __half* __restrict__ aH, long aStride,
    const __half* __restrict__ wH, long wStride,
    const float* __restrict__ bias, long biasStride,
    __half* cH, long cStride,
    float* pool,
    int M, int N, int K, int mode)
{
    int bz = blockIdx.z;
    aH   += (long)bz * aStride;
    wH   += (long)bz * wStride;
    bias += (long)bz * biasStride;

    extern __shared__ __half smem[];

    int m0 = blockIdx.x * BM;
    int n0 = blockIdx.y * BN;
    int tid  = threadIdx.x;
    int lane = tid & 31;
    int warp = tid >> 5;
    int wm = warp & 3;        // 4 m-warps (32 rows)
    int wn = warp >> 2;       // 2 n-warps (64 cols)

    unsigned sBase = (unsigned)__cvta_generic_to_shared(&smem[0]);

    // cp.async mappings
    int aRow = tid >> 2, aChunk = tid & 3;     // A: 128 rows x 4 chunks (x2 iters of 256)
    int bRow = tid >> 4, bChunk = tid & 15;    // B: 32 rows x 16 chunks (x2 iters)

    int ntile = K / BK;

    auto prefetch = [&](int t) {
        int k0 = t * BK;
        unsigned st = (unsigned)(t % NSTAGE) * STAGE_H * 2 + sBase;
        #pragma unroll
        for (int i = 0; i < 2; i++) {
            int row = aRow + i * 64;
            int gm  = m0 + row;
            const __half* src = aH + (long)min(gm, M - 1) * K + k0 + aChunk * 8;
            cp16(st + (unsigned)((row * APITCH + aChunk * 8) * 2), src, gm < M ? 16 : 0);
        }
        unsigned bst = st + (unsigned)(A_ST * 2);
        #pragma unroll
        for (int i = 0; i < 2; i++) {
            int row = bRow + i * 16;
            const __half* src = wH + (long)(k0 + row) * N + n0 + bChunk * 8;
            cp16(bst + (unsigned)((row * BPITCH + bChunk * 8) * 2), src, 16);
        }
    };

    // ldmatrix addresses (within a stage)
    unsigned aAddr[2][2];   // [kstep][mt]
    #pragma unroll
    for (int ks = 0; ks < 2; ks++)
        #pragma unroll
        for (int mt = 0; mt < 2; mt++)
            aAddr[ks][mt] = (unsigned)(((wm * 32 + mt * 16 + (lane & 15)) * APITCH
                                        + ks * 16 + (lane >> 4) * 8) * 2);
    unsigned bAddr[2][4];   // [kstep][ntp]  (each x4t covers 16 cols)
    {
        int krow = (lane & 7) + ((lane >> 3) & 1) * 8;
        int cofs = (lane >> 4) * 8;
        #pragma unroll
        for (int ks = 0; ks < 2; ks++)
            #pragma unroll
            for (int ntp = 0; ntp < 4; ntp++)
                bAddr[ks][ntp] = (unsigned)(((ks * 16 + krow) * BPITCH
                                             + wn * 64 + ntp * 16 + cofs) * 2);
    }

    float acc[2][8][4];
    #pragma unroll
    for (int i = 0; i < 2; i++)
        #pragma unroll
        for (int j = 0; j < 8; j++)
            #pragma unroll
            for (int k = 0; k < 4; k++) acc[i][j][k] = 0.f;

    // prologue: 2 stages in flight
    prefetch(0); CP_COMMIT();
    if (ntile > 1) { prefetch(1); } CP_COMMIT();

    for (int t = 0; t < ntile; t++) {
        CP_WAIT1();
        __syncthreads();
        if (t + 2 < ntile) prefetch(t + 2);
        CP_COMMIT();

        unsigned st  = (unsigned)(t % NSTAGE) * STAGE_H * 2 + sBase;
        unsigned bst = st + (unsigned)(A_ST * 2);

        #pragma unroll
        for (int ks = 0; ks < 2; ks++) {
            unsigned afr[2][4];
            #pragma unroll
            for (int mt = 0; mt < 2; mt++)
                ldsm_x4(afr[mt], st + aAddr[ks][mt]);
            unsigned bfr[4][4];
            #pragma unroll
            for (int ntp = 0; ntp < 4; ntp++)
                ldsm_x4t(bfr[ntp], bst + bAddr[ks][ntp]);
            #pragma unroll
            for (int mt = 0; mt < 2; mt++)
                #pragma unroll
                for (int nt = 0; nt < 8; nt++)
                    mma_f16(acc[mt][nt], afr[mt], &bfr[nt >> 1][(nt & 1) * 2]);
        }
        __syncthreads();
    }

    int g  = lane >> 2;
    int c4 = lane & 3;

    if (mode == 0) {
        cH += (long)bz * cStride;
        #pragma unroll
        for (int mt = 0; mt < 2; mt++) {
            int r0 = m0 + wm * 32 + mt * 16 + g;
            #pragma unroll
            for (int nt = 0; nt < 8; nt++) {
                int col = n0 + wn * 64 + nt * 8 + 2 * c4;
                float bx = bias[col], by = bias[col + 1];
                if (r0 < M) {
                    float v0 = fmaxf(acc[mt][nt][0] + bx, 0.f);
                    float v1 = fmaxf(acc[mt][nt][1] + by, 0.f);
                    *(unsigned*)(cH + (long)r0 * N + col) = pack_h2(v0, v1);
                }
                if (r0 + 8 < M) {
                    float v0 = fmaxf(acc[mt][nt][2] + bx, 0.f);
                    float v1 = fmaxf(acc[mt][nt][3] + by, 0.f);
                    *(unsigned*)(cH + (long)(r0 + 8) * N + col) = pack_h2(v0, v1);
                }
            }
        }
    } else {
        int warpRow0 = m0 + wm * 32;
        if (warpRow0 < M) {
            int sLocal = warpRow0 / Pp;
            int sampA  = bz + sLocal;
            int bnd    = (sLocal + 1) * Pp - warpRow0;
            bool has2  = (bnd < 32) && (warpRow0 + bnd) < M;
            float t0[16], t1[16];
            #pragma unroll
            for (int s = 0; s < 16; s++) { t0[s] = 0.f; t1[s] = 0.f; }
            #pragma unroll
            for (int mt = 0; mt < 2; mt++) {
                int lr0 = mt * 16 + g;
                int lr1 = lr0 + 8;
                bool ok0 = (warpRow0 + lr0) < M;
                bool ok1 = (warpRow0 + lr1) < M;
                #pragma unroll
                for (int nt = 0; nt < 8; nt++) {
                    int col = n0 + wn * 64 + nt * 8 + 2 * c4;
                    float bx = bias[col], by = bias[col + 1];
                    float a0 = fmaxf(acc[mt][nt][0] + bx, 0.f);
                    float a1 = fmaxf(acc[mt][nt][1] + by, 0.f);
                    float a2 = fmaxf(acc[mt][nt][2] + bx, 0.f);
                    float a3 = fmaxf(acc[mt][nt][3] + by, 0.f);
                    int s0 = nt * 2, s1 = nt * 2 + 1;
                    if (ok0) {
                        if (lr0 < bnd) { t0[s0] += a0; t0[s1] += a1; }
                        else           { t1[s0] += a0; t1[s1] += a1; }
                    }
                    if (ok1) {
                        if (lr1 < bnd) { t0[s0] += a2; t0[s1] += a3; }
                        else           { t1[s0] += a2; t1[s1] += a3; }
                    }
                }
            }
            #pragma unroll
            for (int ofs = 4; ofs < 32; ofs <<= 1) {
                #pragma unroll
                for (int s = 0; s < 16; s++)
                    t0[s] += __shfl_xor_sync(0xFFFFFFFFu, t0[s], ofs);
            }
            if (has2) {
                #pragma unroll
                for (int ofs = 4; ofs < 32; ofs <<= 1) {
                    #pragma unroll
                    for (int s = 0; s < 16; s++)
                        t1[s] += __shfl_xor_sync(0xFFFFFFFFu, t1[s], ofs);
                }
            }
            if (lane < 4) {
                const float inv = 1.f / (float)Pp;
                #pragma unroll
                for (int nt = 0; nt < 8; nt++) {
                    #pragma unroll
                    for (int cp = 0; cp < 2; cp++) {
                        int col = n0 + wn * 64 + nt * 8 + 2 * lane + cp;
                        atomicAdd(&pool[(long)sampA * N + col], t0[nt * 2 + cp] * inv);
                        if (has2)
                            atomicAdd(&pool[(long)(sampA + 1) * N + col], t1[nt * 2 + cp] * inv);
                    }
                }
            }
        }
    }
}

// ---------------- small-M GEMM with in-block split-K ----------------
__global__ void rowgemm_kernel(const float* __restrict__ A,
                               const float* __restrict__ W, long wStride,
                               const float* __restrict__ bias, long biasStride,
                               float* __restrict__ C, int N, int K)
{
    int b  = blockIdx.x;
    int nl = threadIdx.x & 31;
    int kg = threadIdx.x >> 5;
    int n  = blockIdx.y * 32 + nl;
    const float* a = A + (long)b * K;
    const float* w = W + (long)b * wStride;
    int kchunk = K / 8;
    float acc = 0.f;
    for (int k = kg * kchunk; k < (kg + 1) * kchunk; k++)
        acc = fmaf(a[k], w[(long)k * N + n], acc);
    __shared__ float red[8][32];
    red[kg][nl] = acc;
    __syncthreads();
    if (kg == 0) {
        float s = acc;
        #pragma unroll
        for (int j = 1; j < 8; j++) s += red[j][nl];
        C[(long)b * N + n] = s + bias[(long)b * biasStride + n];
    }
}

// ---------------- MetaNet ----------------
__global__ void meta_kernel(const float* __restrict__ base,
                            const float* __restrict__ mW1, const float* __restrict__ mb1,
                            const float* __restrict__ mW2, const float* __restrict__ mb2,
                            float* __restrict__ coef)
{
    int b = blockIdx.x;
    __shared__ float br[Ff];
    __shared__ float hid[MHh];
    int t = threadIdx.x;
    for (int i = t; i < Ff; i += MHh) br[i] = base[b * Ff + i];
    __syncthreads();
    float acc = mb1[t];
    for (int e = 0; e < Ff; e++) acc = fmaf(br[e], mW1[e * MHh + t], acc);
    hid[t] = fmaxf(acc, 0.f);
    __syncthreads();
    if (t < Tn) {
        float c = mb2[t];
        for (int j = 0; j < MHh; j++) c = fmaf(hid[j], mW2[j * Tn + t], c);
        coef[b * Tn + t] = c;
    }
}

// ---------------- compose biases (fp32) ----------------
__global__ void compose_kernel(const float* __restrict__ W, const float* __restrict__ dW,
                               const float* __restrict__ coef, float* __restrict__ out, long S)
{
    __shared__ float cs[Bn * Tn];
    if (threadIdx.x < Bn * Tn) cs[threadIdx.x] = coef[threadIdx.x];
    __syncthreads();
    long i = (long)blockIdx.x * blockDim.x + threadIdx.x;
    if (i >= S) return;
    float w = W[i];
    float d[Tn];
    #pragma unroll
    for (int t = 0; t < Tn; t++) d[t] = dW[(long)t * S + i];
    #pragma unroll 4
    for (int b = 0; b < Bn; b++) {
        float v = w;
        #pragma unroll
        for (int t = 0; t < Tn; t++) v = fmaf(cs[b * Tn + t], d[t], v);
        out[(long)b * S + i] = v;
    }
}

// ---------------- compose weights -> fp16 ----------------
__global__ void compose_h(const float* __restrict__ W, const float* __restrict__ dW,
                          const float* __restrict__ coef, __half* __restrict__ oH, long S)
{
    __shared__ float cs[Bn * Tn];
    if (threadIdx.x < Bn * Tn) cs[threadIdx.x] = coef[threadIdx.x];
    __syncthreads();
    long q = (long)blockIdx.x * blockDim.x + threadIdx.x;
    if (q >= S / 4) return;
    long e = q * 4;
    float4 w = *(const float4*)(W + e);
    float4 d[Tn];
    #pragma unroll
    for (int t = 0; t < Tn; t++) d[t] = *(const float4*)(dW + (long)t * S + e);
    for (int b = 0; b < Bn; b++) {
        float4 v = w;
        #pragma unroll
        for (int t = 0; t < Tn; t++) {
            float c = cs[b * Tn + t];
            v.x = fmaf(c, d[t].x, v.x);
            v.y = fmaf(c, d[t].y, v.y);
            v.z = fmaf(c, d[t].z, v.z);
            v.w = fmaf(c, d[t].w, v.w);
        }
        *(uint2*)(oH + (long)b * S + e) = make_uint2(pack_h2(v.x, v.y), pack_h2(v.z, v.w));
    }
}

// ---------------- y[t,b,n] = h2m[b,:] @ dW3[t,:,n] ----------------
#define YNC 16
__global__ void ydw3_kernel(const float* __restrict__ h2m, const float* __restrict__ dW3,
                            float* __restrict__ y)
{
    int t  = blockIdx.y;
    int n0 = blockIdx.x * YNC;
    const float* w = dW3 + (long)t * DHh * Ff;
    __shared__ float sw[16][YNC];
    __shared__ float sh[Bn][16];
    int tid = threadIdx.x;
    int b  = tid >> 3;
    int nl = tid & 7;
    float acc0 = 0.f, acc1 = 0.f;
    for (int k0 = 0; k0 < DHh; k0 += 16) {
        if (tid < 64) {
            int kk = tid >> 2, nq = tid & 3;
            float4 v = *(const float4*)(w + (long)(k0 + kk) * Ff + n0 + nq * 4);
            sw[kk][nq * 4 + 0] = v.x; sw[kk][nq * 4 + 1] = v.y;
            sw[kk][nq * 4 + 2] = v.z; sw[kk][nq * 4 + 3] = v.w;
        }
        if (tid >= 128) {
            int tt = tid - 128;
            int bb = tt >> 2, kq = tt & 3;
            float4 v = *(const float4*)(h2m + (long)bb * DHh + k0 + kq * 4);
            sh[bb][kq * 4 + 0] = v.x; sh[bb][kq * 4 + 1] = v.y;
            sh[bb][kq * 4 + 2] = v.z; sh[bb][kq * 4 + 3] = v.w;
        }
        __syncthreads();
        #pragma unroll
        for (int kk = 0; kk < 16; kk++) {
            float a = sh[b][kk];
            acc0 = fmaf(a, sw[kk][nl * 2 + 0], acc0);
            acc1 = fmaf(a, sw[kk][nl * 2 + 1], acc1);
        }
        __syncthreads();
    }
    long o = ((long)t * Bn + b) * Ff + n0 + nl * 2;
    y[o]     = acc0;
    y[o + 1] = acc1;
}

// ---------------- final combine ----------------
__global__ void combine_kernel(const float* __restrict__ z0, const float* __restrict__ y,
                               const float* __restrict__ coef, const float* __restrict__ db3,
                               float* __restrict__ out)
{
    int i = blockIdx.x * blockDim.x + threadIdx.x;
    if (i >= Bn * Ff) return;
    int b = i / Ff, n = i % Ff;
    float v = z0[i];
    #pragma unroll
    for (int t = 0; t < Tn; t++)
        v = fmaf(coef[b * Tn + t], y[((long)t * Bn + b) * Ff + n] + db3[t * Ff + n], v);
    out[i] = v;
}

// ---------------- launch ----------------
extern "C" void kernel_launch(void* const* d_in, const int* in_sizes, int n_in,
                              void* d_out, int out_size)
{
    const float* x   = (const float*)d_in[0];
    const float* W1  = (const float*)d_in[1];
    const float* b1  = (const float*)d_in[2];
    const float* W2  = (const float*)d_in[3];
    const float* b2  = (const float*)d_in[4];
    const float* W3  = (const float*)d_in[5];
    const float* b3  = (const float*)d_in[6];
    const float* dW1 = (const float*)d_in[7];
    const float* db1 = (const float*)d_in[8];
    const float* dW2 = (const float*)d_in[9];
    const float* db2 = (const float*)d_in[10];
    const float* dW3 = (const float*)d_in[11];
    const float* db3 = (const float*)d_in[12];
    const float* mW1 = (const float*)d_in[13];
    const float* mb1 = (const float*)d_in[14];
    const float* mW2 = (const float*)d_in[15];
    const float* mb2 = (const float*)d_in[16];
    float* out = (float*)d_out;

    __half *pH, *hH, *hbH, *W1sH, *W2sH, *W1bH, *W2bH;
    float *h2m0, *h2m1, *base, *coef, *b1b, *b2b, *z0, *y;
    cudaGetSymbolAddress((void**)&pH,   g_pH);
    cudaGetSymbolAddress((void**)&hH,   g_hH);
    cudaGetSymbolAddress((void**)&hbH,  g_hbH);
    cudaGetSymbolAddress((void**)&W1sH, g_W1sH);
    cudaGetSymbolAddress((void**)&W2sH, g_W2sH);
    cudaGetSymbolAddress((void**)&W1bH, g_W1bH);
    cudaGetSymbolAddress((void**)&W2bH, g_W2bH);
    cudaGetSymbolAddress((void**)&h2m0, g_h2m0);
    cudaGetSymbolAddress((void**)&h2m1, g_h2m1);
    cudaGetSymbolAddress((void**)&base, g_base);
    cudaGetSymbolAddress((void**)&coef, g_coef);
    cudaGetSymbolAddress((void**)&b1b,  g_b1b);
    cudaGetSymbolAddress((void**)&b2b,  g_b2b);
    cudaGetSymbolAddress((void**)&z0,   g_z0);
    cudaGetSymbolAddress((void**)&y,    g_y);

    cudaFuncSetAttribute(mma_gemm4,
                         cudaFuncAttributeMaxDynamicSharedMemorySize, SMEM_BYTES);

    // 1) patchify -> fp16
    {
        long n = (long)BP * Dd / 2;
        patchify_h<<<(unsigned)((n + 255) / 256), 256>>>(x, pH);
    }
    // 2) convert base weights to fp16
    cvt_w<<<(unsigned)(((long)Dd * Dd / 4 + 255) / 256), 256>>>(W1, W1sH, (long)Dd * Dd / 4);
    cvt_w<<<(unsigned)(((long)Dd * DHh / 4 + 255) / 256), 256>>>(W2, W2sH, (long)Dd * DHh / 4);
    // 3) zero pool accumulators
    zero2<<<(Bn * DHh + 255) / 256, 256>>>(h2m0, h2m1, Bn * DHh);

    // 4) base layer1: h = relu(p @ W1 + b1)
    mma_gemm4<<<dim3(BP / BM, Dd / BN, 1), 256, SMEM_BYTES>>>(
        pH, 0, W1sH, 0, b1, 0,
        hH, 0, nullptr, BP, Dd, Dd, 0);

    // 5) base layer2 + fused mean-pool -> h2m0
    mma_gemm4<<<dim3(BP / BM, DHh / BN, 1), 256, SMEM_BYTES>>>(
        hH, 0, W2sH, 0, b2, 0,
        nullptr, 0, h2m0, BP, DHh, Dd, 1);

    // 6) base = h2m0 @ W3 + b3
    rowgemm_kernel<<<dim3(Bn, Ff / 32), 256>>>(h2m0, W3, 0, b3, 0, base, Ff, DHh);

    // 7) MetaNet -> coefs
    meta_kernel<<<Bn, MHh>>>(base, mW1, mb1, mW2, mb2, coef);

    // 8) compose biases + weights (fp16)
    compose_kernel<<<(Dd  + 255) / 256, 256>>>(b1, db1, coef, b1b, Dd);
    compose_kernel<<<(DHh + 255) / 256, 256>>>(b2, db2, coef, b2b, DHh);
    {
        long S1 = (long)Dd * Dd;
        long S2 = (long)Dd * DHh;
        compose_h<<<(unsigned)((S1 / 4 + 255) / 256), 256>>>(W1, dW1, coef, W1bH, S1);
        compose_h<<<(unsigned)((S2 / 4 + 255) / 256), 256>>>(W2, dW2, coef, W2bH, S2);
    }

    // 9) adapted layer1 (batched): hb = relu(p @ W1b + b1b)
    mma_gemm4<<<dim3((Pp + BM - 1) / BM, Dd / BN, Bn), 256, SMEM_BYTES>>>(
        pH,   (long)Pp * Dd,
        W1bH, (long)Dd * Dd,
        b1b,  (long)Dd,
        hbH,  (long)Pp * Dd, nullptr,
        Pp, Dd, Dd, 0);

    // 10) adapted layer2 + fused mean-pool -> h2m1
    mma_gemm4<<<dim3((Pp + BM - 1) / BM, DHh / BN, Bn), 256, SMEM_BYTES>>>(
        hbH,  (long)Pp * Dd,
        W2bH, (long)Dd * DHh,
        b2b,  (long)DHh,
        nullptr, 0, h2m1,
        Pp, DHh, Dd, 1);

    // 11) z0 = h2m1 @ W3 + b3
    rowgemm_kernel<<<dim3(Bn, Ff / 32), 256>>>(h2m1, W3, 0, b3, 0, z0, Ff, DHh);

    // 12) y[t,b,:] = h2m1[b,:] @ dW3[t]
    ydw3_kernel<<<dim3(Ff / YNC, Tn), 256>>>(h2m1, dW3, y);

    // 13) out = z0 + sum_t coef*(y + db3)
    combine_kernel<<<(Bn * Ff + 255) / 256, 256>>>(z0, y, coef, db3, out);
}